// round 5
// baseline (speedup 1.0000x reference)
#include <cuda_runtime.h>
#include <cuda_bf16.h>
#include <cuda_fp16.h>

// ---------------------------------------------------------------------------
// 2-layer GCN via CSR aggregation:
//   y = dinv[row] * (x W)     (tf32 mma GEMM, fragment-layout smem, fp16 out)
//   out[d] = dinv[d]*(y[d] + sum_{s->d} y[s]) + b   (warp-per-row gather)
//
// RULE: __device__ globals are ONLY referenced from device code (kernel
// bodies). Never passed as kernel arguments from kernel_launch (host code).
// ---------------------------------------------------------------------------

#define MAX_NODES 50048
#define MAX_EDGES 1048576
#define D_IN   256
#define D_HID  256
#define D_OUT  128
#define SCAN_B ((MAX_NODES + 255) / 256)

__device__ float  g_dinv[MAX_NODES];
__device__ int    g_cnt [MAX_NODES];
__device__ int    g_tmp [MAX_NODES];
__device__ int    g_bsum[SCAN_B];
__device__ int    g_rowptr[MAX_NODES + 1];
__device__ int    g_wofs[MAX_NODES];
__device__ int    g_col [MAX_EDGES];
__device__ __half g_y1h[(size_t)MAX_NODES * D_HID];
__device__ float  g_h  [(size_t)MAX_NODES * D_HID];
__device__ __half g_y2h[(size_t)MAX_NODES * D_OUT];

// ---------------------------------------------------------------------------
// CSR build
// ---------------------------------------------------------------------------
__global__ void zero_cnt_kernel(int n) {
    int i = blockIdx.x * blockDim.x + threadIdx.x;
    if (i < n) g_cnt[i] = 0;
}

__global__ void count_kernel(const int* __restrict__ ei, int n_edges) {
    int e = blockIdx.x * blockDim.x + threadIdx.x;
    if (e < n_edges) atomicAdd(&g_cnt[ei[n_edges + e]], 1);
}

__global__ void scan1_kernel(int n) {
    __shared__ int sh[256];
    int i = blockIdx.x * 256 + threadIdx.x;
    int v = (i < n) ? g_cnt[i] : 0;
    sh[threadIdx.x] = v;
    __syncthreads();
#pragma unroll
    for (int off = 1; off < 256; off <<= 1) {
        int t = (threadIdx.x >= off) ? sh[threadIdx.x - off] : 0;
        __syncthreads();
        sh[threadIdx.x] += t;
        __syncthreads();
    }
    if (i < n) g_tmp[i] = sh[threadIdx.x];
    if (threadIdx.x == 255) g_bsum[blockIdx.x] = sh[255];
}

__global__ void scan2_kernel(int nb) {
    __shared__ int sh[256];
    int t = threadIdx.x;
    int v = (t < nb) ? g_bsum[t] : 0;
    sh[t] = v;
    __syncthreads();
#pragma unroll
    for (int off = 1; off < 256; off <<= 1) {
        int u = (t >= off) ? sh[t - off] : 0;
        __syncthreads();
        sh[t] += u;
        __syncthreads();
    }
    int ex = (t == 0) ? 0 : sh[t - 1];
    if (t < nb) g_bsum[t] = ex;
}

__global__ void scan3_kernel(int n) {
    int i = blockIdx.x * 256 + threadIdx.x;
    if (i < n) {
        int incl = g_tmp[i] + g_bsum[blockIdx.x];
        g_rowptr[i + 1] = incl;
        g_wofs[i] = incl - g_cnt[i];
        g_dinv[i] = rsqrtf((float)(g_cnt[i] + 1));   // +1 self-loop
        if (i == 0) g_rowptr[0] = 0;
    }
}

__global__ void fill_kernel(const int* __restrict__ ei, int n_edges) {
    int e = blockIdx.x * blockDim.x + threadIdx.x;
    if (e < n_edges) {
        int dst = ei[n_edges + e];
        int pos = atomicAdd(&g_wofs[dst], 1);
        g_col[pos] = ei[e];
    }
}

// ---------------------------------------------------------------------------
// TF32 tensor-core GEMM, fragment-order shared memory.
// BM=128, BN=128, BK=32, 512 threads, warp grid 4m x 4n, warp tile 32x32.
//
// A smem: subtile (msub 0..7, ksub 0..3) of 16m x 8k, stored so thread
//   lane reads its 4 fragment regs as one uint4:  idx = sub*128 + lane*4 + reg
// B smem: subtile (nsub 0..15, ksub 0..3) of 8n x 8k:
//   idx = sub*64 + lane*2 + reg   (uint2 per thread)
// ---------------------------------------------------------------------------
__device__ __forceinline__ unsigned f2tf32(float x) {
    unsigned u;
    asm("cvt.rna.tf32.f32 %0, %1;" : "=r"(u) : "f"(x));
    return u;
}

__device__ __forceinline__ void mma_tf32(float c[4],
                                         unsigned a0, unsigned a1,
                                         unsigned a2, unsigned a3,
                                         unsigned b0, unsigned b1) {
    asm volatile(
        "mma.sync.aligned.m16n8k8.row.col.f32.tf32.tf32.f32 "
        "{%0,%1,%2,%3}, {%4,%5,%6,%7}, {%8,%9}, {%0,%1,%2,%3};"
        : "+f"(c[0]), "+f"(c[1]), "+f"(c[2]), "+f"(c[3])
        : "r"(a0), "r"(a1), "r"(a2), "r"(a3), "r"(b0), "r"(b1));
}

__device__ __forceinline__ void mma_gemm_body(const float* __restrict__ A,
                                              const float* __restrict__ B,
                                              const float* __restrict__ dinv,
                                              __half* __restrict__ Yh,
                                              int M, int N, int K)
{
    __shared__ unsigned As[4096];   // 128m x 32k
    __shared__ unsigned Bs[4096];   // 32k x 128n

    const int tid   = threadIdx.x;
    const int lane  = tid & 31;
    const int warp  = tid >> 5;              // 0..15
    const int bm    = blockIdx.x * 128;
    const int bn    = blockIdx.y * 128;
    const int wmsub = (warp & 3) * 2;        // 2 m-subtiles per warp
    const int wnsub = (warp >> 2) * 4;       // 4 n-subtiles per warp

    // ---- loader precompute (2 float4 chunks each for A and B) ----
    const float* aptr[2]; bool aok[2]; int abase[2];
    const float* bptr[2]; int bbase[2];
#pragma unroll
    for (int u = 0; u < 2; u++) {
        int id = u * 512 + tid;              // 0..1023
        // A: r = row (0..127), kc = k col (0,4,..,28)
        int r = id >> 3, kc = (id & 7) << 2;
        aok[u]  = (bm + r) < M;
        aptr[u] = A + (size_t)(bm + r) * K + kc;
        {
            int msub = r >> 4, row16 = r & 15;
            int g = row16 & 7, rhi = row16 >> 3;
            int ksub = kc >> 3, khalf = (kc >> 2) & 1;
            abase[u] = (msub * 4 + ksub) * 128 + g * 16 + rhi + 2 * khalf;
            // elements t=0..3 go to abase + 4*t
        }
        // B: k = 0..31, ncol = 0,4,..,124
        int k = id >> 5, ncol = (id & 31) << 2;
        bptr[u] = B + (size_t)k * N + bn + ncol;
        {
            int nsub = ncol >> 3, n8 = ncol & 7;
            int tig = k & 3, reg = (k & 7) >> 2, ksub = k >> 3;
            bbase[u] = (nsub * 4 + ksub) * 64 + (n8 * 4 + tig) * 2 + reg;
            // elements t=0..3 go to bbase + 8*t
        }
    }

    float acc[2][4][4];
#pragma unroll
    for (int mt = 0; mt < 2; mt++)
#pragma unroll
        for (int nt = 0; nt < 4; nt++)
#pragma unroll
            for (int q = 0; q < 4; q++) acc[mt][nt][q] = 0.0f;

    const int nk = K / 32;
    float4 pa[2], pb[2];

    // ---- prologue: tile 0 ----
#pragma unroll
    for (int u = 0; u < 2; u++) {
        pa[u] = aok[u] ? *reinterpret_cast<const float4*>(aptr[u])
                       : make_float4(0.f, 0.f, 0.f, 0.f);
        pb[u] = *reinterpret_cast<const float4*>(bptr[u]);
    }
#pragma unroll
    for (int u = 0; u < 2; u++) {
        unsigned* p = &As[abase[u]];
        p[0] = f2tf32(pa[u].x); p[4]  = f2tf32(pa[u].y);
        p[8] = f2tf32(pa[u].z); p[12] = f2tf32(pa[u].w);
        unsigned* q = &Bs[bbase[u]];
        q[0]  = f2tf32(pb[u].x); q[8]  = f2tf32(pb[u].y);
        q[16] = f2tf32(pb[u].z); q[24] = f2tf32(pb[u].w);
    }
    __syncthreads();

    for (int t = 0; t < nk; t++) {
        if (t + 1 < nk) {
            const int ko = (t + 1) * 32;
#pragma unroll
            for (int u = 0; u < 2; u++) {
                pa[u] = aok[u] ? *reinterpret_cast<const float4*>(aptr[u] + ko)
                               : make_float4(0.f, 0.f, 0.f, 0.f);
                pb[u] = *reinterpret_cast<const float4*>(bptr[u] + (size_t)ko * N);
            }
        }

        // ---- compute: 4 k-steps of 8 ----
#pragma unroll
        for (int ks = 0; ks < 4; ks++) {
            uint4 af0 = *reinterpret_cast<const uint4*>(
                &As[((wmsub + 0) * 4 + ks) * 128 + lane * 4]);
            uint4 af1 = *reinterpret_cast<const uint4*>(
                &As[((wmsub + 1) * 4 + ks) * 128 + lane * 4]);
            uint2 bf[4];
#pragma unroll
            for (int nt = 0; nt < 4; nt++)
                bf[nt] = *reinterpret_cast<const uint2*>(
                    &Bs[((wnsub + nt) * 4 + ks) * 64 + lane * 2]);
#pragma unroll
            for (int nt = 0; nt < 4; nt++) {
                mma_tf32(acc[0][nt], af0.x, af0.y, af0.z, af0.w, bf[nt].x, bf[nt].y);
                mma_tf32(acc[1][nt], af1.x, af1.y, af1.z, af1.w, bf[nt].x, bf[nt].y);
            }
        }

        if (t + 1 < nk) {
            __syncthreads();
#pragma unroll
            for (int u = 0; u < 2; u++) {
                unsigned* p = &As[abase[u]];
                p[0] = f2tf32(pa[u].x); p[4]  = f2tf32(pa[u].y);
                p[8] = f2tf32(pa[u].z); p[12] = f2tf32(pa[u].w);
                unsigned* q = &Bs[bbase[u]];
                q[0]  = f2tf32(pb[u].x); q[8]  = f2tf32(pb[u].y);
                q[16] = f2tf32(pb[u].z); q[24] = f2tf32(pb[u].w);
            }
            __syncthreads();
        }
    }

    // ---- epilogue: scale by dinv, store fp16 ----
    const int g = lane >> 2, tig = lane & 3;
#pragma unroll
    for (int mt = 0; mt < 2; mt++) {
        int r0 = bm + (wmsub + mt) * 16 + g;
        int r1 = r0 + 8;
        float s0 = (r0 < M) ? dinv[r0] : 0.f;
        float s1 = (r1 < M) ? dinv[r1] : 0.f;
#pragma unroll
        for (int nt = 0; nt < 4; nt++) {
            int c = bn + (wnsub + nt) * 8 + 2 * tig;
            if (r0 < M)
                *reinterpret_cast<__half2*>(Yh + (size_t)r0 * N + c) =
                    __floats2half2_rn(s0 * acc[mt][nt][0], s0 * acc[mt][nt][1]);
            if (r1 < M)
                *reinterpret_cast<__half2*>(Yh + (size_t)r1 * N + c) =
                    __floats2half2_rn(s1 * acc[mt][nt][2], s1 * acc[mt][nt][3]);
        }
    }
}

__global__ __launch_bounds__(512) void gemm1_kernel(const float* __restrict__ z,
                                                    const float* __restrict__ W1,
                                                    int M)
{
    mma_gemm_body(z, W1, g_dinv, g_y1h, M, D_HID, D_IN);
}

__global__ __launch_bounds__(512) void gemm2_kernel(const float* __restrict__ W2,
                                                    int M)
{
    mma_gemm_body(g_h, W2, g_dinv, g_y2h, M, D_OUT, D_HID);
}

// ---------------------------------------------------------------------------
// CSR aggregation from fp16 y: OUT[d] = dinv[d]*(y[d] + sum y[s]) + bias
// One warp per node; fp32 accumulation.
// ---------------------------------------------------------------------------
__device__ __forceinline__ void h8_add(float a[8], uint4 u) {
    float2 f;
    f = __half22float2(*reinterpret_cast<const __half2*>(&u.x)); a[0] += f.x; a[1] += f.y;
    f = __half22float2(*reinterpret_cast<const __half2*>(&u.y)); a[2] += f.x; a[3] += f.y;
    f = __half22float2(*reinterpret_cast<const __half2*>(&u.z)); a[4] += f.x; a[5] += f.y;
    f = __half22float2(*reinterpret_cast<const __half2*>(&u.w)); a[6] += f.x; a[7] += f.y;
}

__device__ __forceinline__ void h4_add(float a[4], uint2 u) {
    float2 f;
    f = __half22float2(*reinterpret_cast<const __half2*>(&u.x)); a[0] += f.x; a[1] += f.y;
    f = __half22float2(*reinterpret_cast<const __half2*>(&u.y)); a[2] += f.x; a[3] += f.y;
}

// D=256, relu, fp32 out
__device__ __forceinline__ void agg1_body(const __half* __restrict__ Y,
                                          float* __restrict__ OUT,
                                          const float* __restrict__ bias,
                                          int n_nodes)
{
    const int node = (blockIdx.x * blockDim.x + threadIdx.x) >> 5;
    const int lane = threadIdx.x & 31;
    if (node >= n_nodes) return;

    const uint4* Yv = reinterpret_cast<const uint4*>(Y);  // 8 halves per uint4
    float a[8];
    {
        uint4 u = Yv[(size_t)node * 32 + lane];           // self-loop
        float2 f;
        f = __half22float2(*reinterpret_cast<const __half2*>(&u.x)); a[0] = f.x; a[1] = f.y;
        f = __half22float2(*reinterpret_cast<const __half2*>(&u.y)); a[2] = f.x; a[3] = f.y;
        f = __half22float2(*reinterpret_cast<const __half2*>(&u.z)); a[4] = f.x; a[5] = f.y;
        f = __half22float2(*reinterpret_cast<const __half2*>(&u.w)); a[6] = f.x; a[7] = f.y;
    }
    const int e0 = g_rowptr[node];
    const int e1 = g_rowptr[node + 1];

    int e = e0;
    if (e + 1 < e1) {
        uint4 v0 = Yv[(size_t)g_col[e]     * 32 + lane];
        uint4 v1 = Yv[(size_t)g_col[e + 1] * 32 + lane];
        e += 2;
        for (; e + 1 < e1; e += 2) {
            uint4 w0 = Yv[(size_t)g_col[e]     * 32 + lane];
            uint4 w1 = Yv[(size_t)g_col[e + 1] * 32 + lane];
            h8_add(a, v0); h8_add(a, v1);
            v0 = w0; v1 = w1;
        }
        h8_add(a, v0); h8_add(a, v1);
    }
    if (e < e1) h8_add(a, Yv[(size_t)g_col[e] * 32 + lane]);

    const float s = g_dinv[node];
    const float4* bv = reinterpret_cast<const float4*>(bias);
    float4 b0 = bv[lane * 2], b1 = bv[lane * 2 + 1];
    float4 o0, o1;
    o0.x = fmaxf(fmaf(s, a[0], b0.x), 0.f);
    o0.y = fmaxf(fmaf(s, a[1], b0.y), 0.f);
    o0.z = fmaxf(fmaf(s, a[2], b0.z), 0.f);
    o0.w = fmaxf(fmaf(s, a[3], b0.w), 0.f);
    o1.x = fmaxf(fmaf(s, a[4], b1.x), 0.f);
    o1.y = fmaxf(fmaf(s, a[5], b1.y), 0.f);
    o1.z = fmaxf(fmaf(s, a[6], b1.z), 0.f);
    o1.w = fmaxf(fmaf(s, a[7], b1.w), 0.f);
    float4* op = reinterpret_cast<float4*>(OUT + (size_t)node * 256) + lane * 2;
    op[0] = o0; op[1] = o1;
}

// D=128, no relu, fp32 out
__device__ __forceinline__ void agg2_body(const __half* __restrict__ Y,
                                          float* __restrict__ OUT,
                                          const float* __restrict__ bias,
                                          int n_nodes)
{
    const int node = (blockIdx.x * blockDim.x + threadIdx.x) >> 5;
    const int lane = threadIdx.x & 31;
    if (node >= n_nodes) return;

    const uint2* Yv = reinterpret_cast<const uint2*>(Y);  // 4 halves per uint2
    float a[4];
    {
        uint2 u = Yv[(size_t)node * 32 + lane];
        float2 f;
        f = __half22float2(*reinterpret_cast<const __half2*>(&u.x)); a[0] = f.x; a[1] = f.y;
        f = __half22float2(*reinterpret_cast<const __half2*>(&u.y)); a[2] = f.x; a[3] = f.y;
    }
    const int e0 = g_rowptr[node];
    const int e1 = g_rowptr[node + 1];

    int e = e0;
    if (e + 1 < e1) {
        uint2 v0 = Yv[(size_t)g_col[e]     * 32 + lane];
        uint2 v1 = Yv[(size_t)g_col[e + 1] * 32 + lane];
        e += 2;
        for (; e + 1 < e1; e += 2) {
            uint2 w0 = Yv[(size_t)g_col[e]     * 32 + lane];
            uint2 w1 = Yv[(size_t)g_col[e + 1] * 32 + lane];
            h4_add(a, v0); h4_add(a, v1);
            v0 = w0; v1 = w1;
        }
        h4_add(a, v0); h4_add(a, v1);
    }
    if (e < e1) h4_add(a, Yv[(size_t)g_col[e] * 32 + lane]);

    const float s = g_dinv[node];
    float4 b = reinterpret_cast<const float4*>(bias)[lane];
    float4 o;
    o.x = fmaf(s, a[0], b.x);
    o.y = fmaf(s, a[1], b.y);
    o.z = fmaf(s, a[2], b.z);
    o.w = fmaf(s, a[3], b.w);
    reinterpret_cast<float4*>(OUT + (size_t)node * 128)[lane] = o;
}

__global__ __launch_bounds__(256) void agg1_kernel(const float* __restrict__ bias,
                                                   int n_nodes)
{
    agg1_body(g_y1h, g_h, bias, n_nodes);
}

__global__ __launch_bounds__(256) void agg2_kernel(float* __restrict__ out,
                                                   const float* __restrict__ bias,
                                                   int n_nodes)
{
    agg2_body(g_y2h, out, bias, n_nodes);
}

// ---------------------------------------------------------------------------
extern "C" void kernel_launch(void* const* d_in, const int* in_sizes, int n_in,
                              void* d_out, int out_size)
{
    const float* z   = (const float*)d_in[0];
    const int*   ei  = (const int*)  d_in[1];
    const float* W1  = (const float*)d_in[2];
    const float* b1  = (const float*)d_in[3];
    const float* W2  = (const float*)d_in[4];
    const float* b2  = (const float*)d_in[5];
    float* out = (float*)d_out;

    const int n_nodes = in_sizes[0] / D_IN;
    const int n_edges = in_sizes[1] / 2;
    const int T   = 256;
    const int nbN = (n_nodes + T - 1) / T;
    const int nbE = (n_edges + T - 1) / T;

    // ---- CSR build + dinv ----
    zero_cnt_kernel<<<nbN, T>>>(n_nodes);
    count_kernel<<<nbE, T>>>(ei, n_edges);
    scan1_kernel<<<nbN, T>>>(n_nodes);
    scan2_kernel<<<1, T>>>(nbN);
    scan3_kernel<<<nbN, T>>>(n_nodes);
    fill_kernel<<<nbE, T>>>(ei, n_edges);

    const unsigned aggB = (unsigned)(((long long)n_nodes * 32 + T - 1) / T);

    // ---- layer 1 ----
    {
        dim3 grid((n_nodes + 127) / 128, D_HID / 128);
        gemm1_kernel<<<grid, 512>>>(z, W1, n_nodes);
    }
    agg1_kernel<<<aggB, T>>>(b1, n_nodes);

    // ---- layer 2 ----
    {
        dim3 grid((n_nodes + 127) / 128, D_OUT / 128);
        gemm2_kernel<<<grid, 512>>>(W2, n_nodes);
    }
    agg2_kernel<<<aggB, T>>>(out, b2, n_nodes);
}

// round 6
// speedup vs baseline: 1.6962x; 1.6962x over previous
#include <cuda_runtime.h>
#include <cuda_bf16.h>
#include <cuda_fp16.h>

// ---------------------------------------------------------------------------
// 2-layer GCN via CSR aggregation:
//   y = dinv[row] * (x W)         (tf32 mma GEMM — ROUND-4 PROVEN VERSION,
//                                  epilogue now emits fp16)
//   out[d] = dinv[d]*(y[d] + sum_{s->d} y[s]) + b   (warp-per-row fp16 gather)
//
// RULE: __device__ globals are ONLY referenced from device code.
// ---------------------------------------------------------------------------

#define MAX_NODES 50048
#define MAX_EDGES 1048576
#define D_IN   256
#define D_HID  256
#define D_OUT  128
#define SCAN_B ((MAX_NODES + 255) / 256)

__device__ float  g_dinv[MAX_NODES];
__device__ int    g_cnt [MAX_NODES];
__device__ int    g_tmp [MAX_NODES];
__device__ int    g_bsum[SCAN_B];
__device__ int    g_rowptr[MAX_NODES + 1];
__device__ int    g_wofs[MAX_NODES];
__device__ int    g_col [MAX_EDGES];
__device__ __half g_y1h[(size_t)MAX_NODES * D_HID];
__device__ float  g_h  [(size_t)MAX_NODES * D_HID];
__device__ __half g_y2h[(size_t)MAX_NODES * D_OUT];

// ---------------------------------------------------------------------------
// CSR build
// ---------------------------------------------------------------------------
__global__ void zero_cnt_kernel(int n) {
    int i = blockIdx.x * blockDim.x + threadIdx.x;
    if (i < n) g_cnt[i] = 0;
}

__global__ void count_kernel(const int* __restrict__ ei, int n_edges) {
    int e = blockIdx.x * blockDim.x + threadIdx.x;
    if (e < n_edges) atomicAdd(&g_cnt[ei[n_edges + e]], 1);
}

__global__ void scan1_kernel(int n) {
    __shared__ int sh[256];
    int i = blockIdx.x * 256 + threadIdx.x;
    int v = (i < n) ? g_cnt[i] : 0;
    sh[threadIdx.x] = v;
    __syncthreads();
#pragma unroll
    for (int off = 1; off < 256; off <<= 1) {
        int t = (threadIdx.x >= off) ? sh[threadIdx.x - off] : 0;
        __syncthreads();
        sh[threadIdx.x] += t;
        __syncthreads();
    }
    if (i < n) g_tmp[i] = sh[threadIdx.x];
    if (threadIdx.x == 255) g_bsum[blockIdx.x] = sh[255];
}

__global__ void scan2_kernel(int nb) {
    __shared__ int sh[256];
    int t = threadIdx.x;
    int v = (t < nb) ? g_bsum[t] : 0;
    sh[t] = v;
    __syncthreads();
#pragma unroll
    for (int off = 1; off < 256; off <<= 1) {
        int u = (t >= off) ? sh[t - off] : 0;
        __syncthreads();
        sh[t] += u;
        __syncthreads();
    }
    int ex = (t == 0) ? 0 : sh[t - 1];
    if (t < nb) g_bsum[t] = ex;
}

__global__ void scan3_kernel(int n) {
    int i = blockIdx.x * 256 + threadIdx.x;
    if (i < n) {
        int incl = g_tmp[i] + g_bsum[blockIdx.x];
        g_rowptr[i + 1] = incl;
        g_wofs[i] = incl - g_cnt[i];
        g_dinv[i] = rsqrtf((float)(g_cnt[i] + 1));   // +1 self-loop
        if (i == 0) g_rowptr[0] = 0;
    }
}

__global__ void fill_kernel(const int* __restrict__ ei, int n_edges) {
    int e = blockIdx.x * blockDim.x + threadIdx.x;
    if (e < n_edges) {
        int dst = ei[n_edges + e];
        int pos = atomicAdd(&g_wofs[dst], 1);
        g_col[pos] = ei[e];
    }
}

// ---------------------------------------------------------------------------
// TF32 tensor-core GEMM (round-4 proven): Y = dinv[m] * (A @ B), fp16 out.
// BM=128, BN=128, BK=16, 256 threads, warp grid 4x2, warp tile 32x64,
// double-buffered smem [k][m]/[k][n] with +4 pad.
// ---------------------------------------------------------------------------
__device__ __forceinline__ unsigned f2tf32(float x) {
    unsigned u;
    asm("cvt.rna.tf32.f32 %0, %1;" : "=r"(u) : "f"(x));
    return u;
}

__device__ __forceinline__ void mma_tf32(float c[4],
                                         unsigned a0, unsigned a1,
                                         unsigned a2, unsigned a3,
                                         unsigned b0, unsigned b1) {
    asm volatile(
        "mma.sync.aligned.m16n8k8.row.col.f32.tf32.tf32.f32 "
        "{%0,%1,%2,%3}, {%4,%5,%6,%7}, {%8,%9}, {%0,%1,%2,%3};"
        : "+f"(c[0]), "+f"(c[1]), "+f"(c[2]), "+f"(c[3])
        : "r"(a0), "r"(a1), "r"(a2), "r"(a3), "r"(b0), "r"(b1));
}

__device__ __forceinline__ void mma_gemm_body(const float* __restrict__ A,
                                              const float* __restrict__ B,
                                              const float* __restrict__ dinv,
                                              __half* __restrict__ Yh,
                                              int M, int N, int K)
{
    __shared__ unsigned As[2][16][132];
    __shared__ unsigned Bs[2][16][132];

    const int tid  = threadIdx.x;
    const int lane = tid & 31;
    const int warp = tid >> 5;
    const int g    = lane >> 2;
    const int tig  = lane & 3;
    const int wm   = (warp & 3) * 32;
    const int wn   = (warp >> 2) * 64;
    const int bm   = blockIdx.x * 128;
    const int bn   = blockIdx.y * 128;

    float acc[2][8][4];
#pragma unroll
    for (int mt = 0; mt < 2; mt++)
#pragma unroll
        for (int nt = 0; nt < 8; nt++)
#pragma unroll
            for (int q = 0; q < 4; q++) acc[mt][nt][q] = 0.0f;

    const int nk = K / 16;
    float4 pa[2], pb[2];

    {
#pragma unroll
        for (int u = 0; u < 2; u++) {
            int i = 2 * tid + u;
            int r = i >> 2, kc = (i & 3) << 2;
            int gr = bm + r;
            float4 v = make_float4(0.f, 0.f, 0.f, 0.f);
            if (gr < M) v = *reinterpret_cast<const float4*>(A + (size_t)gr * K + kc);
            pa[u] = v;
            int k = i >> 5, n4 = i & 31;
            pb[u] = *reinterpret_cast<const float4*>(B + (size_t)k * N + bn + n4 * 4);
        }
#pragma unroll
        for (int u = 0; u < 2; u++) {
            int i = 2 * tid + u;
            int r = i >> 2, kc = (i & 3) << 2;
            As[0][kc + 0][r] = f2tf32(pa[u].x);
            As[0][kc + 1][r] = f2tf32(pa[u].y);
            As[0][kc + 2][r] = f2tf32(pa[u].z);
            As[0][kc + 3][r] = f2tf32(pa[u].w);
            int k = i >> 5, n4 = i & 31;
            unsigned* p = &Bs[0][k][n4 * 4];
            p[0] = f2tf32(pb[u].x);
            p[1] = f2tf32(pb[u].y);
            p[2] = f2tf32(pb[u].z);
            p[3] = f2tf32(pb[u].w);
        }
    }
    __syncthreads();

    int cur = 0;
    for (int t = 0; t < nk; t++) {
        if (t + 1 < nk) {
            int k0 = (t + 1) * 16;
#pragma unroll
            for (int u = 0; u < 2; u++) {
                int i = 2 * tid + u;
                int r = i >> 2, kc = (i & 3) << 2;
                int gr = bm + r;
                float4 v = make_float4(0.f, 0.f, 0.f, 0.f);
                if (gr < M) v = *reinterpret_cast<const float4*>(A + (size_t)gr * K + k0 + kc);
                pa[u] = v;
                int k = i >> 5, n4 = i & 31;
                pb[u] = *reinterpret_cast<const float4*>(B + (size_t)(k0 + k) * N + bn + n4 * 4);
            }
        }

#pragma unroll
        for (int ks = 0; ks < 2; ks++) {
            const int k = ks * 8;
            unsigned af[2][4];
#pragma unroll
            for (int mt = 0; mt < 2; mt++) {
                int mb = wm + mt * 16 + g;
                af[mt][0] = As[cur][k + tig][mb];
                af[mt][1] = As[cur][k + tig][mb + 8];
                af[mt][2] = As[cur][k + tig + 4][mb];
                af[mt][3] = As[cur][k + tig + 4][mb + 8];
            }
            unsigned bf[8][2];
#pragma unroll
            for (int nt = 0; nt < 8; nt++) {
                int nb = wn + nt * 8 + g;
                bf[nt][0] = Bs[cur][k + tig][nb];
                bf[nt][1] = Bs[cur][k + tig + 4][nb];
            }
#pragma unroll
            for (int mt = 0; mt < 2; mt++)
#pragma unroll
                for (int nt = 0; nt < 8; nt++)
                    mma_tf32(acc[mt][nt],
                             af[mt][0], af[mt][1], af[mt][2], af[mt][3],
                             bf[nt][0], bf[nt][1]);
        }

        if (t + 1 < nk) {
            int nxt = cur ^ 1;
#pragma unroll
            for (int u = 0; u < 2; u++) {
                int i = 2 * tid + u;
                int r = i >> 2, kc = (i & 3) << 2;
                As[nxt][kc + 0][r] = f2tf32(pa[u].x);
                As[nxt][kc + 1][r] = f2tf32(pa[u].y);
                As[nxt][kc + 2][r] = f2tf32(pa[u].z);
                As[nxt][kc + 3][r] = f2tf32(pa[u].w);
                int k = i >> 5, n4 = i & 31;
                unsigned* p = &Bs[nxt][k][n4 * 4];
                p[0] = f2tf32(pb[u].x);
                p[1] = f2tf32(pb[u].y);
                p[2] = f2tf32(pb[u].z);
                p[3] = f2tf32(pb[u].w);
            }
            __syncthreads();
            cur = nxt;
        }
    }

    // ---- epilogue: scale by dinv, store fp16 ----
#pragma unroll
    for (int mt = 0; mt < 2; mt++) {
        int r0 = bm + wm + mt * 16 + g;
        int r1 = r0 + 8;
        float s0 = (r0 < M) ? dinv[r0] : 0.0f;
        float s1 = (r1 < M) ? dinv[r1] : 0.0f;
#pragma unroll
        for (int nt = 0; nt < 8; nt++) {
            int c = bn + wn + nt * 8 + 2 * tig;
            if (r0 < M)
                *reinterpret_cast<__half2*>(Yh + (size_t)r0 * N + c) =
                    __floats2half2_rn(s0 * acc[mt][nt][0], s0 * acc[mt][nt][1]);
            if (r1 < M)
                *reinterpret_cast<__half2*>(Yh + (size_t)r1 * N + c) =
                    __floats2half2_rn(s1 * acc[mt][nt][2], s1 * acc[mt][nt][3]);
        }
    }
}

__global__ __launch_bounds__(256) void gemm1_kernel(const float* __restrict__ z,
                                                    const float* __restrict__ W1,
                                                    int M)
{
    mma_gemm_body(z, W1, g_dinv, g_y1h, M, D_HID, D_IN);
}

__global__ __launch_bounds__(256) void gemm2_kernel(const float* __restrict__ W2,
                                                    int M)
{
    mma_gemm_body(g_h, W2, g_dinv, g_y2h, M, D_OUT, D_HID);
}

// ---------------------------------------------------------------------------
// CSR aggregation from fp16 y: OUT[d] = dinv[d]*(y[d] + sum y[s]) + bias
// One warp per node; fp32 accumulation.
// ---------------------------------------------------------------------------
__device__ __forceinline__ void h8_add(float a[8], uint4 u) {
    float2 f;
    f = __half22float2(*reinterpret_cast<const __half2*>(&u.x)); a[0] += f.x; a[1] += f.y;
    f = __half22float2(*reinterpret_cast<const __half2*>(&u.y)); a[2] += f.x; a[3] += f.y;
    f = __half22float2(*reinterpret_cast<const __half2*>(&u.z)); a[4] += f.x; a[5] += f.y;
    f = __half22float2(*reinterpret_cast<const __half2*>(&u.w)); a[6] += f.x; a[7] += f.y;
}

__device__ __forceinline__ void h4_add(float a[4], uint2 u) {
    float2 f;
    f = __half22float2(*reinterpret_cast<const __half2*>(&u.x)); a[0] += f.x; a[1] += f.y;
    f = __half22float2(*reinterpret_cast<const __half2*>(&u.y)); a[2] += f.x; a[3] += f.y;
}

// D=256, relu, fp32 out
__device__ __forceinline__ void agg1_body(const __half* __restrict__ Y,
                                          float* __restrict__ OUT,
                                          const float* __restrict__ bias,
                                          int n_nodes)
{
    const int node = (blockIdx.x * blockDim.x + threadIdx.x) >> 5;
    const int lane = threadIdx.x & 31;
    if (node >= n_nodes) return;

    const uint4* Yv = reinterpret_cast<const uint4*>(Y);  // 8 halves per uint4
    float a[8];
    {
        uint4 u = Yv[(size_t)node * 32 + lane];           // self-loop
        float2 f;
        f = __half22float2(*reinterpret_cast<const __half2*>(&u.x)); a[0] = f.x; a[1] = f.y;
        f = __half22float2(*reinterpret_cast<const __half2*>(&u.y)); a[2] = f.x; a[3] = f.y;
        f = __half22float2(*reinterpret_cast<const __half2*>(&u.z)); a[4] = f.x; a[5] = f.y;
        f = __half22float2(*reinterpret_cast<const __half2*>(&u.w)); a[6] = f.x; a[7] = f.y;
    }
    const int e0 = g_rowptr[node];
    const int e1 = g_rowptr[node + 1];

    int e = e0;
    if (e + 1 < e1) {
        uint4 v0 = Yv[(size_t)g_col[e]     * 32 + lane];
        uint4 v1 = Yv[(size_t)g_col[e + 1] * 32 + lane];
        e += 2;
        for (; e + 1 < e1; e += 2) {
            uint4 w0 = Yv[(size_t)g_col[e]     * 32 + lane];
            uint4 w1 = Yv[(size_t)g_col[e + 1] * 32 + lane];
            h8_add(a, v0); h8_add(a, v1);
            v0 = w0; v1 = w1;
        }
        h8_add(a, v0); h8_add(a, v1);
    }
    if (e < e1) h8_add(a, Yv[(size_t)g_col[e] * 32 + lane]);

    const float s = g_dinv[node];
    const float4* bv = reinterpret_cast<const float4*>(bias);
    float4 b0 = bv[lane * 2], b1 = bv[lane * 2 + 1];
    float4 o0, o1;
    o0.x = fmaxf(fmaf(s, a[0], b0.x), 0.f);
    o0.y = fmaxf(fmaf(s, a[1], b0.y), 0.f);
    o0.z = fmaxf(fmaf(s, a[2], b0.z), 0.f);
    o0.w = fmaxf(fmaf(s, a[3], b0.w), 0.f);
    o1.x = fmaxf(fmaf(s, a[4], b1.x), 0.f);
    o1.y = fmaxf(fmaf(s, a[5], b1.y), 0.f);
    o1.z = fmaxf(fmaf(s, a[6], b1.z), 0.f);
    o1.w = fmaxf(fmaf(s, a[7], b1.w), 0.f);
    float4* op = reinterpret_cast<float4*>(OUT + (size_t)node * 256) + lane * 2;
    op[0] = o0; op[1] = o1;
}

// D=128, no relu, fp32 out
__device__ __forceinline__ void agg2_body(const __half* __restrict__ Y,
                                          float* __restrict__ OUT,
                                          const float* __restrict__ bias,
                                          int n_nodes)
{
    const int node = (blockIdx.x * blockDim.x + threadIdx.x) >> 5;
    const int lane = threadIdx.x & 31;
    if (node >= n_nodes) return;

    const uint2* Yv = reinterpret_cast<const uint2*>(Y);  // 4 halves per uint2
    float a[4];
    {
        uint2 u = Yv[(size_t)node * 32 + lane];
        float2 f;
        f = __half22float2(*reinterpret_cast<const __half2*>(&u.x)); a[0] = f.x; a[1] = f.y;
        f = __half22float2(*reinterpret_cast<const __half2*>(&u.y)); a[2] = f.x; a[3] = f.y;
    }
    const int e0 = g_rowptr[node];
    const int e1 = g_rowptr[node + 1];

    int e = e0;
    if (e + 1 < e1) {
        uint2 v0 = Yv[(size_t)g_col[e]     * 32 + lane];
        uint2 v1 = Yv[(size_t)g_col[e + 1] * 32 + lane];
        e += 2;
        for (; e + 1 < e1; e += 2) {
            uint2 w0 = Yv[(size_t)g_col[e]     * 32 + lane];
            uint2 w1 = Yv[(size_t)g_col[e + 1] * 32 + lane];
            h4_add(a, v0); h4_add(a, v1);
            v0 = w0; v1 = w1;
        }
        h4_add(a, v0); h4_add(a, v1);
    }
    if (e < e1) h4_add(a, Yv[(size_t)g_col[e] * 32 + lane]);

    const float s = g_dinv[node];
    float4 b = reinterpret_cast<const float4*>(bias)[lane];
    float4 o;
    o.x = fmaf(s, a[0], b.x);
    o.y = fmaf(s, a[1], b.y);
    o.z = fmaf(s, a[2], b.z);
    o.w = fmaf(s, a[3], b.w);
    reinterpret_cast<float4*>(OUT + (size_t)node * 128)[lane] = o;
}

__global__ __launch_bounds__(256) void agg1_kernel(const float* __restrict__ bias,
                                                   int n_nodes)
{
    agg1_body(g_y1h, g_h, bias, n_nodes);
}

__global__ __launch_bounds__(256) void agg2_kernel(float* __restrict__ out,
                                                   const float* __restrict__ bias,
                                                   int n_nodes)
{
    agg2_body(g_y2h, out, bias, n_nodes);
}

// ---------------------------------------------------------------------------
extern "C" void kernel_launch(void* const* d_in, const int* in_sizes, int n_in,
                              void* d_out, int out_size)
{
    const float* z   = (const float*)d_in[0];
    const int*   ei  = (const int*)  d_in[1];
    const float* W1  = (const float*)d_in[2];
    const float* b1  = (const float*)d_in[3];
    const float* W2  = (const float*)d_in[4];
    const float* b2  = (const float*)d_in[5];
    float* out = (float*)d_out;

    const int n_nodes = in_sizes[0] / D_IN;
    const int n_edges = in_sizes[1] / 2;
    const int T   = 256;
    const int nbN = (n_nodes + T - 1) / T;
    const int nbE = (n_edges + T - 1) / T;

    // ---- CSR build + dinv ----
    zero_cnt_kernel<<<nbN, T>>>(n_nodes);
    count_kernel<<<nbE, T>>>(ei, n_edges);
    scan1_kernel<<<nbN, T>>>(n_nodes);
    scan2_kernel<<<1, T>>>(nbN);
    scan3_kernel<<<nbN, T>>>(n_nodes);
    fill_kernel<<<nbE, T>>>(ei, n_edges);

    const unsigned aggB = (unsigned)(((long long)n_nodes * 32 + T - 1) / T);

    // ---- layer 1 ----
    {
        dim3 grid((n_nodes + 127) / 128, D_HID / 128);
        gemm1_kernel<<<grid, 256>>>(z, W1, n_nodes);
    }
    agg1_kernel<<<aggB, T>>>(b1, n_nodes);

    // ---- layer 2 ----
    {
        dim3 grid((n_nodes + 127) / 128, D_OUT / 128);
        gemm2_kernel<<<grid, 256>>>(W2, n_nodes);
    }
    agg2_kernel<<<aggB, T>>>(out, b2, n_nodes);
}

// round 8
// speedup vs baseline: 2.3874x; 1.4075x over previous
#include <cuda_runtime.h>
#include <cuda_bf16.h>
#include <cuda_fp16.h>

// ---------------------------------------------------------------------------
// 2-layer GCN via CSR aggregation:
//   y = dinv[row] * (x W)      (fp16 mma m16n8k16 GEMM, fp32 accum, fp16 out)
//   out[d] = dinv[d]*(y[d] + sum_{s->d} y[s]) + b   (warp-per-row fp16 gather)
// fp16 mantissa == tf32 mantissa (10 bits) -> no extra error vs tf32 path.
//
// RULE: __device__ globals are ONLY referenced from device code.
// ---------------------------------------------------------------------------

#define MAX_NODES 50048
#define MAX_EDGES 1048576
#define D_IN   256
#define D_HID  256
#define D_OUT  128
#define SCAN_B ((MAX_NODES + 255) / 256)

__device__ float  g_dinv[MAX_NODES];
__device__ int    g_cnt [MAX_NODES];
__device__ int    g_tmp [MAX_NODES];
__device__ int    g_bsum[SCAN_B];
__device__ int    g_rowptr[MAX_NODES + 1];
__device__ int    g_wofs[MAX_NODES];
__device__ int    g_col [MAX_EDGES];
__device__ __half g_y1h[(size_t)MAX_NODES * D_HID];
__device__ __half g_hh [(size_t)MAX_NODES * D_HID];   // h stored fp16
__device__ __half g_y2h[(size_t)MAX_NODES * D_OUT];

// ---------------------------------------------------------------------------
// CSR build
// ---------------------------------------------------------------------------
__global__ void zero_cnt_kernel(int n) {
    int i = blockIdx.x * blockDim.x + threadIdx.x;
    if (i < n) g_cnt[i] = 0;
}

__global__ void count_kernel(const int* __restrict__ ei, int n_edges) {
    int e = blockIdx.x * blockDim.x + threadIdx.x;
    if (e < n_edges) atomicAdd(&g_cnt[ei[n_edges + e]], 1);
}

__global__ void scan1_kernel(int n) {
    __shared__ int sh[256];
    int i = blockIdx.x * 256 + threadIdx.x;
    int v = (i < n) ? g_cnt[i] : 0;
    sh[threadIdx.x] = v;
    __syncthreads();
#pragma unroll
    for (int off = 1; off < 256; off <<= 1) {
        int t = (threadIdx.x >= off) ? sh[threadIdx.x - off] : 0;
        __syncthreads();
        sh[threadIdx.x] += t;
        __syncthreads();
    }
    if (i < n) g_tmp[i] = sh[threadIdx.x];
    if (threadIdx.x == 255) g_bsum[blockIdx.x] = sh[255];
}

__global__ void scan2_kernel(int nb) {
    __shared__ int sh[256];
    int t = threadIdx.x;
    int v = (t < nb) ? g_bsum[t] : 0;
    sh[t] = v;
    __syncthreads();
#pragma unroll
    for (int off = 1; off < 256; off <<= 1) {
        int u = (t >= off) ? sh[t - off] : 0;
        __syncthreads();
        sh[t] += u;
        __syncthreads();
    }
    int ex = (t == 0) ? 0 : sh[t - 1];
    if (t < nb) g_bsum[t] = ex;
}

__global__ void scan3_kernel(int n) {
    int i = blockIdx.x * 256 + threadIdx.x;
    if (i < n) {
        int incl = g_tmp[i] + g_bsum[blockIdx.x];
        g_rowptr[i + 1] = incl;
        g_wofs[i] = incl - g_cnt[i];
        g_dinv[i] = rsqrtf((float)(g_cnt[i] + 1));   // +1 self-loop
        if (i == 0) g_rowptr[0] = 0;
    }
}

__global__ void fill_kernel(const int* __restrict__ ei, int n_edges) {
    int e = blockIdx.x * blockDim.x + threadIdx.x;
    if (e < n_edges) {
        int dst = ei[n_edges + e];
        int pos = atomicAdd(&g_wofs[dst], 1);
        g_col[pos] = ei[e];
    }
}

// ---------------------------------------------------------------------------
// fp16 tensor-core GEMM: Y = dinv[m] * (A @ B), fp32 accumulate, fp16 out.
// BM=128, BN=128, BK=32 (two m16n8k16 k-steps), 256 threads, warp grid 4x2,
// warp tile 32x64. Double-buffered smem; word = half2 (K-pair), layout
// [k2][m] / [k2][n] with +4 pad (round-4 proven structure, k scaled by 2).
// ---------------------------------------------------------------------------
__device__ __forceinline__ unsigned f2h2(float lo, float hi) {
    __half2 h = __floats2half2_rn(lo, hi);
    return *reinterpret_cast<unsigned*>(&h);
}

__device__ __forceinline__ void mma_f16(float c[4],
                                        unsigned a0, unsigned a1,
                                        unsigned a2, unsigned a3,
                                        unsigned b0, unsigned b1) {
    asm volatile(
        "mma.sync.aligned.m16n8k16.row.col.f32.f16.f16.f32 "
        "{%0,%1,%2,%3}, {%4,%5,%6,%7}, {%8,%9}, {%0,%1,%2,%3};"
        : "+f"(c[0]), "+f"(c[1]), "+f"(c[2]), "+f"(c[3])
        : "r"(a0), "r"(a1), "r"(a2), "r"(a3), "r"(b0), "r"(b1));
}

template<bool AHALF>
__device__ __forceinline__ void mma_gemm_body(const void* __restrict__ Araw,
                                              const float* __restrict__ B,
                                              const float* __restrict__ dinv,
                                              __half* __restrict__ Yh,
                                              int M, int N, int K)
{
    __shared__ unsigned As[2][16][132];   // [k2][m], k2 = k/2
    __shared__ unsigned Bs[2][16][132];   // [k2][n]

    const int tid  = threadIdx.x;
    const int lane = tid & 31;
    const int warp = tid >> 5;
    const int g    = lane >> 2;
    const int tig  = lane & 3;
    const int wm   = (warp & 3) * 32;
    const int wn   = (warp >> 2) * 64;
    const int bm   = blockIdx.x * 128;
    const int bn   = blockIdx.y * 128;

    float acc[2][8][4];
#pragma unroll
    for (int mt = 0; mt < 2; mt++)
#pragma unroll
        for (int nt = 0; nt < 8; nt++)
#pragma unroll
            for (int q = 0; q < 4; q++) acc[mt][nt][q] = 0.0f;

    const int nk = K / 32;

    // ---- loader precompute ----
    // A fp32: 4 units (float4 each) ; A fp16: 2 units (uint4 each)
    int af_r[4], af_k2[4]; bool af_ok[4]; const float* af_p[4];
    int ah_r[2], ah_k2[2]; bool ah_ok[2]; const uint4* ah_p[2];
    if constexpr (!AHALF) {
        const float* A = (const float*)Araw;
#pragma unroll
        for (int u = 0; u < 4; u++) {
            int id = u * 256 + tid;               // 0..1023
            int r = id >> 3, kc = (id & 7) << 2;  // row, k col (0,4,..,28)
            af_r[u] = r; af_k2[u] = kc >> 1;
            af_ok[u] = (bm + r) < M;
            af_p[u] = A + (size_t)(bm + r) * K + kc;
        }
    } else {
        const __half* A = (const __half*)Araw;
#pragma unroll
        for (int u = 0; u < 2; u++) {
            int id = u * 256 + tid;               // 0..511
            int r = id >> 2, q = id & 3;          // row, uint4 idx (8 halves)
            ah_r[u] = r; ah_k2[u] = q * 4;
            ah_ok[u] = (bm + r) < M;
            ah_p[u] = reinterpret_cast<const uint4*>(A + (size_t)(bm + r) * K) + q;
        }
    }
    int b_k2[2], b_n4[2]; const float* b_p[2];
#pragma unroll
    for (int u = 0; u < 2; u++) {
        int id = u * 256 + tid;                   // 0..511
        b_k2[u] = id >> 5; b_n4[u] = (id & 31) << 2;
        b_p[u] = B + (size_t)(2 * b_k2[u]) * N + bn + b_n4[u];
    }

    // staging regs
    float4 paf[4]; uint4 pah[2];
    float4 pb0[2], pb1[2];

    // ---- fetch tile t into staging regs ----
    auto fetch = [&](int t) {
        if constexpr (!AHALF) {
            const int ko = t * 32;
#pragma unroll
            for (int u = 0; u < 4; u++)
                paf[u] = af_ok[u] ? *reinterpret_cast<const float4*>(af_p[u] + ko)
                                  : make_float4(0.f, 0.f, 0.f, 0.f);
        } else {
#pragma unroll
            for (int u = 0; u < 2; u++)
                pah[u] = ah_ok[u] ? ah_p[u][4 * t]
                                  : make_uint4(0u, 0u, 0u, 0u);
        }
        const size_t bo = (size_t)(32 * t) * N;
#pragma unroll
        for (int u = 0; u < 2; u++) {
            pb0[u] = *reinterpret_cast<const float4*>(b_p[u] + bo);
            pb1[u] = *reinterpret_cast<const float4*>(b_p[u] + bo + N);
        }
    };

    // ---- store staging regs into smem buffer ----
    auto store = [&](int buf) {
        if constexpr (!AHALF) {
#pragma unroll
            for (int u = 0; u < 4; u++) {
                As[buf][af_k2[u] + 0][af_r[u]] = f2h2(paf[u].x, paf[u].y);
                As[buf][af_k2[u] + 1][af_r[u]] = f2h2(paf[u].z, paf[u].w);
            }
        } else {
#pragma unroll
            for (int u = 0; u < 2; u++) {
                As[buf][ah_k2[u] + 0][ah_r[u]] = pah[u].x;
                As[buf][ah_k2[u] + 1][ah_r[u]] = pah[u].y;
                As[buf][ah_k2[u] + 2][ah_r[u]] = pah[u].z;
                As[buf][ah_k2[u] + 3][ah_r[u]] = pah[u].w;
            }
        }
#pragma unroll
        for (int u = 0; u < 2; u++) {
            uint4 w;
            w.x = f2h2(pb0[u].x, pb1[u].x);
            w.y = f2h2(pb0[u].y, pb1[u].y);
            w.z = f2h2(pb0[u].z, pb1[u].z);
            w.w = f2h2(pb0[u].w, pb1[u].w);
            *reinterpret_cast<uint4*>(&Bs[buf][b_k2[u]][b_n4[u]]) = w;
        }
    };

    fetch(0);
    store(0);
    __syncthreads();

    int cur = 0;
    for (int t = 0; t < nk; t++) {
        if (t + 1 < nk) fetch(t + 1);

        // ---- compute: 2 k16-steps ----
#pragma unroll
        for (int ks = 0; ks < 2; ks++) {
            const int k2b = ks * 8;
            unsigned af[2][4];
#pragma unroll
            for (int mt = 0; mt < 2; mt++) {
                int mb = wm + mt * 16 + g;
                af[mt][0] = As[cur][k2b + tig][mb];
                af[mt][1] = As[cur][k2b + tig][mb + 8];
                af[mt][2] = As[cur][k2b + tig + 4][mb];
                af[mt][3] = As[cur][k2b + tig + 4][mb + 8];
            }
            unsigned bf[8][2];
#pragma unroll
            for (int nt = 0; nt < 8; nt++) {
                int nb = wn + nt * 8 + g;
                bf[nt][0] = Bs[cur][k2b + tig][nb];
                bf[nt][1] = Bs[cur][k2b + tig + 4][nb];
            }
#pragma unroll
            for (int mt = 0; mt < 2; mt++)
#pragma unroll
                for (int nt = 0; nt < 8; nt++)
                    mma_f16(acc[mt][nt],
                            af[mt][0], af[mt][1], af[mt][2], af[mt][3],
                            bf[nt][0], bf[nt][1]);
        }

        if (t + 1 < nk) {
            int nxt = cur ^ 1;
            store(nxt);
            __syncthreads();
            cur = nxt;
        }
    }

    // ---- epilogue: scale by dinv, store fp16 ----
#pragma unroll
    for (int mt = 0; mt < 2; mt++) {
        int r0 = bm + wm + mt * 16 + g;
        int r1 = r0 + 8;
        float s0 = (r0 < M) ? dinv[r0] : 0.0f;
        float s1 = (r1 < M) ? dinv[r1] : 0.0f;
#pragma unroll
        for (int nt = 0; nt < 8; nt++) {
            int c = bn + wn + nt * 8 + 2 * tig;
            if (r0 < M)
                *reinterpret_cast<__half2*>(Yh + (size_t)r0 * N + c) =
                    __floats2half2_rn(s0 * acc[mt][nt][0], s0 * acc[mt][nt][1]);
            if (r1 < M)
                *reinterpret_cast<__half2*>(Yh + (size_t)r1 * N + c) =
                    __floats2half2_rn(s1 * acc[mt][nt][2], s1 * acc[mt][nt][3]);
        }
    }
}

__global__ __launch_bounds__(256) void gemm1_kernel(const float* __restrict__ z,
                                                    const float* __restrict__ W1,
                                                    int M)
{
    mma_gemm_body<false>(z, W1, g_dinv, g_y1h, M, D_HID, D_IN);
}

__global__ __launch_bounds__(256) void gemm2_kernel(const float* __restrict__ W2,
                                                    int M)
{
    mma_gemm_body<true>(g_hh, W2, g_dinv, g_y2h, M, D_OUT, D_HID);
}

// ---------------------------------------------------------------------------
// CSR aggregation from fp16 y: OUT[d] = dinv[d]*(y[d] + sum y[s]) + bias
// One warp per node; fp32 accumulation.
// ---------------------------------------------------------------------------
__device__ __forceinline__ void h8_add(float a[8], uint4 u) {
    float2 f;
    f = __half22float2(*reinterpret_cast<const __half2*>(&u.x)); a[0] += f.x; a[1] += f.y;
    f = __half22float2(*reinterpret_cast<const __half2*>(&u.y)); a[2] += f.x; a[3] += f.y;
    f = __half22float2(*reinterpret_cast<const __half2*>(&u.z)); a[4] += f.x; a[5] += f.y;
    f = __half22float2(*reinterpret_cast<const __half2*>(&u.w)); a[6] += f.x; a[7] += f.y;
}

__device__ __forceinline__ void h4_add(float a[4], uint2 u) {
    float2 f;
    f = __half22float2(*reinterpret_cast<const __half2*>(&u.x)); a[0] += f.x; a[1] += f.y;
    f = __half22float2(*reinterpret_cast<const __half2*>(&u.y)); a[2] += f.x; a[3] += f.y;
}

// D=256, relu, fp16 out (feeds gemm2; gemm2 would convert to fp16 anyway)
__device__ __forceinline__ void agg1_body(const __half* __restrict__ Y,
                                          __half* __restrict__ OUT,
                                          const float* __restrict__ bias,
                                          int n_nodes)
{
    const int node = (blockIdx.x * blockDim.x + threadIdx.x) >> 5;
    const int lane = threadIdx.x & 31;
    if (node >= n_nodes) return;

    const uint4* Yv = reinterpret_cast<const uint4*>(Y);  // 8 halves per uint4
    float a[8];
    {
        uint4 u = Yv[(size_t)node * 32 + lane];           // self-loop
        float2 f;
        f = __half22float2(*reinterpret_cast<const __half2*>(&u.x)); a[0] = f.x; a[1] = f.y;
        f = __half22float2(*reinterpret_cast<const __half2*>(&u.y)); a[2] = f.x; a[3] = f.y;
        f = __half22float2(*reinterpret_cast<const __half2*>(&u.z)); a[4] = f.x; a[5] = f.y;
        f = __half22float2(*reinterpret_cast<const __half2*>(&u.w)); a[6] = f.x; a[7] = f.y;
    }
    const int e0 = g_rowptr[node];
    const int e1 = g_rowptr[node + 1];

    int e = e0;
    if (e + 1 < e1) {
        uint4 v0 = Yv[(size_t)g_col[e]     * 32 + lane];
        uint4 v1 = Yv[(size_t)g_col[e + 1] * 32 + lane];
        e += 2;
        for (; e + 1 < e1; e += 2) {
            uint4 w0 = Yv[(size_t)g_col[e]     * 32 + lane];
            uint4 w1 = Yv[(size_t)g_col[e + 1] * 32 + lane];
            h8_add(a, v0); h8_add(a, v1);
            v0 = w0; v1 = w1;
        }
        h8_add(a, v0); h8_add(a, v1);
    }
    if (e < e1) h8_add(a, Yv[(size_t)g_col[e] * 32 + lane]);

    const float s = g_dinv[node];
    const float4* bv = reinterpret_cast<const float4*>(bias);
    float4 b0 = bv[lane * 2], b1 = bv[lane * 2 + 1];
    float o[8];
    o[0] = fmaxf(fmaf(s, a[0], b0.x), 0.f);
    o[1] = fmaxf(fmaf(s, a[1], b0.y), 0.f);
    o[2] = fmaxf(fmaf(s, a[2], b0.z), 0.f);
    o[3] = fmaxf(fmaf(s, a[3], b0.w), 0.f);
    o[4] = fmaxf(fmaf(s, a[4], b1.x), 0.f);
    o[5] = fmaxf(fmaf(s, a[5], b1.y), 0.f);
    o[6] = fmaxf(fmaf(s, a[6], b1.z), 0.f);
    o[7] = fmaxf(fmaf(s, a[7], b1.w), 0.f);
    uint4 w;
    w.x = f2h2(o[0], o[1]);
    w.y = f2h2(o[2], o[3]);
    w.z = f2h2(o[4], o[5]);
    w.w = f2h2(o[6], o[7]);
    reinterpret_cast<uint4*>(OUT + (size_t)node * 256)[lane] = w;
}

// D=128, no relu, fp32 out (final output)
__device__ __forceinline__ void agg2_body(const __half* __restrict__ Y,
                                          float* __restrict__ OUT,
                                          const float* __restrict__ bias,
                                          int n_nodes)
{
    const int node = (blockIdx.x * blockDim.x + threadIdx.x) >> 5;
    const int lane = threadIdx.x & 31;
    if (node >= n_nodes) return;

    const uint2* Yv = reinterpret_cast<const uint2*>(Y);  // 4 halves per uint2
    float a[4];
    {
        uint2 u = Yv[(size_t)node * 32 + lane];
        float2 f;
        f = __half22float2(*reinterpret_cast<const __half2*>(&u.x)); a[0] = f.x; a[1] = f.y;
        f = __half22float2(*reinterpret_cast<const __half2*>(&u.y)); a[2] = f.x; a[3] = f.y;
    }
    const int e0 = g_rowptr[node];
    const int e1 = g_rowptr[node + 1];

    int e = e0;
    if (e + 1 < e1) {
        uint2 v0 = Yv[(size_t)g_col[e]     * 32 + lane];
        uint2 v1 = Yv[(size_t)g_col[e + 1] * 32 + lane];
        e += 2;
        for (; e + 1 < e1; e += 2) {
            uint2 w0 = Yv[(size_t)g_col[e]     * 32 + lane];
            uint2 w1 = Yv[(size_t)g_col[e + 1] * 32 + lane];
            h4_add(a, v0); h4_add(a, v1);
            v0 = w0; v1 = w1;
        }
        h4_add(a, v0); h4_add(a, v1);
    }
    if (e < e1) h4_add(a, Yv[(size_t)g_col[e] * 32 + lane]);

    const float s = g_dinv[node];
    float4 b = reinterpret_cast<const float4*>(bias)[lane];
    float4 o;
    o.x = fmaf(s, a[0], b.x);
    o.y = fmaf(s, a[1], b.y);
    o.z = fmaf(s, a[2], b.z);
    o.w = fmaf(s, a[3], b.w);
    reinterpret_cast<float4*>(OUT + (size_t)node * 128)[lane] = o;
}

__global__ __launch_bounds__(256) void agg1_kernel(const float* __restrict__ bias,
                                                   int n_nodes)
{
    agg1_body(g_y1h, g_hh, bias, n_nodes);
}

__global__ __launch_bounds__(256) void agg2_kernel(float* __restrict__ out,
                                                   const float* __restrict__ bias,
                                                   int n_nodes)
{
    agg2_body(g_y2h, out, bias, n_nodes);
}

// ---------------------------------------------------------------------------
extern "C" void kernel_launch(void* const* d_in, const int* in_sizes, int n_in,
                              void* d_out, int out_size)
{
    const float* z   = (const float*)d_in[0];
    const int*   ei  = (const int*)  d_in[1];
    const float* W1  = (const float*)d_in[2];
    const float* b1  = (const float*)d_in[3];
    const float* W2  = (const float*)d_in[4];
    const float* b2  = (const float*)d_in[5];
    float* out = (float*)d_out;

    const int n_nodes = in_sizes[0] / D_IN;
    const int n_edges = in_sizes[1] / 2;
    const int T   = 256;
    const int nbN = (n_nodes + T - 1) / T;
    const int nbE = (n_edges + T - 1) / T;

    // ---- CSR build + dinv ----
    zero_cnt_kernel<<<nbN, T>>>(n_nodes);
    count_kernel<<<nbE, T>>>(ei, n_edges);
    scan1_kernel<<<nbN, T>>>(n_nodes);
    scan2_kernel<<<1, T>>>(nbN);
    scan3_kernel<<<nbN, T>>>(n_nodes);
    fill_kernel<<<nbE, T>>>(ei, n_edges);

    const unsigned aggB = (unsigned)(((long long)n_nodes * 32 + T - 1) / T);

    // ---- layer 1 ----
    {
        dim3 grid((n_nodes + 127) / 128, D_HID / 128);
        gemm1_kernel<<<grid, 256>>>(z, W1, n_nodes);
    }
    agg1_kernel<<<aggB, T>>>(b1, n_nodes);

    // ---- layer 2 ----
    {
        dim3 grid((n_nodes + 127) / 128, D_OUT / 128);
        gemm2_kernel<<<grid, 256>>>(W2, n_nodes);
    }
    agg2_kernel<<<aggB, T>>>(out, b2, n_nodes);
}

// round 11
// speedup vs baseline: 2.4821x; 1.0397x over previous
#include <cuda_runtime.h>
#include <cuda_fp16.h>
#include <cstdint>

// ---------------------------------------------------------------------------
// 2-layer GCN (sm_103 target: mma.sync HMMA path; tcgen05 unavailable).
//   y1 = z W1 (UNSCALED, fp16)    -- ldmatrix + m16n8k16 GEMM, count fused
//   h  = relu(dinv[d]*(dinv[d]*y1[d] + sum dinv[s]*y1[s]) + b1)
//   y2 = dinv * (h W2) (fp16)
//   out= dinv[d]*(y2[d] + sum y2[s]) + b2
// RULE: __device__ globals only referenced from device code.
// ---------------------------------------------------------------------------

#define MAX_NODES 50048
#define MAX_EDGES 1048576
#define D_IN   256
#define D_HID  256
#define D_OUT  128
#define SCAN_B ((MAX_NODES + 255) / 256)

__device__ float  g_dinv[MAX_NODES];
__device__ int    g_cnt [MAX_NODES];
__device__ int    g_tmp [MAX_NODES];
__device__ int    g_bsum[SCAN_B];
__device__ int    g_rowptr[MAX_NODES + 1];
__device__ int    g_wofs[MAX_NODES];
__device__ int    g_col [MAX_EDGES];
__device__ __half g_y1h[(size_t)MAX_NODES * D_HID];   // UNSCALED z@W1
__device__ __half g_hh [(size_t)MAX_NODES * D_HID];
__device__ __half g_y2h[(size_t)MAX_NODES * D_OUT];   // dinv-scaled h@W2
__device__ __half g_w1t[D_HID * D_IN];    // W1^T fp16 [n][k]
__device__ __half g_w2t[D_OUT * D_HID];   // W2^T fp16 [n][k]

// ---------------------------------------------------------------------------
__device__ __forceinline__ uint32_t smem_u32(const void* p) {
    uint32_t a;
    asm("{ .reg .u64 t; cvta.to.shared.u64 t, %1; cvt.u32.u64 %0, t; }"
        : "=r"(a) : "l"(p));
    return a;
}

__device__ __forceinline__ unsigned f2h2(float lo, float hi) {
    __half2 h = __floats2half2_rn(lo, hi);
    return *reinterpret_cast<unsigned*>(&h);
}

__device__ __forceinline__ void mma_f16(float c[4],
                                        unsigned a0, unsigned a1,
                                        unsigned a2, unsigned a3,
                                        unsigned b0, unsigned b1) {
    asm volatile(
        "mma.sync.aligned.m16n8k16.row.col.f32.f16.f16.f32 "
        "{%0,%1,%2,%3}, {%4,%5,%6,%7}, {%8,%9}, {%0,%1,%2,%3};"
        : "+f"(c[0]), "+f"(c[1]), "+f"(c[2]), "+f"(c[3])
        : "r"(a0), "r"(a1), "r"(a2), "r"(a3), "r"(b0), "r"(b1));
}

__device__ __forceinline__ void ldsm4(uint32_t addr, uint32_t r[4]) {
    asm volatile("ldmatrix.sync.aligned.m8n8.x4.shared.b16 {%0,%1,%2,%3}, [%4];"
                 : "=r"(r[0]), "=r"(r[1]), "=r"(r[2]), "=r"(r[3]) : "r"(addr));
}

// ---------------------------------------------------------------------------
// prep: zero degree counters + pack W1^T, W2^T fp16
// ---------------------------------------------------------------------------
__global__ void prep_kernel(const float* __restrict__ W1,
                            const float* __restrict__ W2, int n_nodes) {
    int i = blockIdx.x * blockDim.x + threadIdx.x;
    if (i < n_nodes) { g_cnt[i] = 0; return; }
    int j = i - n_nodes;
    if (j < D_HID * D_IN) {
        int n = j >> 8, k = j & 255;
        g_w1t[j] = __float2half_rn(W1[k * D_HID + n]);
        return;
    }
    j -= D_HID * D_IN;
    if (j < D_OUT * D_HID) {
        int n = j >> 8, k = j & 255;
        g_w2t[j] = __float2half_rn(W2[k * D_OUT + n]);
    }
}

// ---------------------------------------------------------------------------
// scan chain (proven)
// ---------------------------------------------------------------------------
__global__ void scan1_kernel(int n) {
    __shared__ int sh[256];
    int i = blockIdx.x * 256 + threadIdx.x;
    int v = (i < n) ? g_cnt[i] : 0;
    sh[threadIdx.x] = v;
    __syncthreads();
#pragma unroll
    for (int off = 1; off < 256; off <<= 1) {
        int t = (threadIdx.x >= off) ? sh[threadIdx.x - off] : 0;
        __syncthreads();
        sh[threadIdx.x] += t;
        __syncthreads();
    }
    if (i < n) g_tmp[i] = sh[threadIdx.x];
    if (threadIdx.x == 255) g_bsum[blockIdx.x] = sh[255];
}
__global__ void scan2_kernel(int nb) {
    __shared__ int sh[256];
    int t = threadIdx.x;
    int v = (t < nb) ? g_bsum[t] : 0;
    sh[t] = v;
    __syncthreads();
#pragma unroll
    for (int off = 1; off < 256; off <<= 1) {
        int u = (t >= off) ? sh[t - off] : 0;
        __syncthreads();
        sh[t] += u;
        __syncthreads();
    }
    int ex = (t == 0) ? 0 : sh[t - 1];
    if (t < nb) g_bsum[t] = ex;
}
__global__ void scan3_kernel(int n) {
    int i = blockIdx.x * 256 + threadIdx.x;
    if (i < n) {
        int incl = g_tmp[i] + g_bsum[blockIdx.x];
        g_rowptr[i + 1] = incl;
        g_wofs[i] = incl - g_cnt[i];
        g_dinv[i] = rsqrtf((float)(g_cnt[i] + 1));
        if (i == 0) g_rowptr[0] = 0;
    }
}
__global__ void fill_kernel(const int* __restrict__ ei, int n_edges) {
    int e = blockIdx.x * blockDim.x + threadIdx.x;
    if (e < n_edges) {
        int dst = ei[n_edges + e];
        int pos = atomicAdd(&g_wofs[dst], 1);
        g_col[pos] = ei[e];
    }
}

// ---------------------------------------------------------------------------
// fp16 mma GEMM with ldmatrix fragment loads.
// BM=128, BN=128, BK=32, K=256, 256 threads, warp grid 4m x 2n, warp 32x64.
// Smem tiles: row-major, 64B pitch (32 halves/row), 16B-chunk swizzle
//   chunk' = chunk ^ ((row>>1)&3);   A bufs @0/@8192, B bufs @16384/@24576.
// ---------------------------------------------------------------------------
template<bool AHALF, bool SCALE>
__device__ __forceinline__ void gemm_body(const void* __restrict__ Araw,
                                          const __half* __restrict__ Bt,
                                          __half* __restrict__ Yh,
                                          int M, int Nrow)
{
    __shared__ __align__(128) char sm[32768];
    const uint32_t sb = smem_u32(sm);
    const int tid  = threadIdx.x;
    const int lane = tid & 31;
    const int warp = tid >> 5;
    const int bm   = blockIdx.x * 128;
    const int bn   = blockIdx.y * 128;
    const int wm   = (warp & 3) * 32;
    const int wn   = (warp >> 2) * 64;

    // ---- ldmatrix base addresses (buffer 0, ks=0) ----
    uint32_t apre[2], bpre[4];
    {
        const int l = lane;
        const int mrl = ((l >> 3) & 1) * 8 + (l & 7);   // A: row-low bits
        const int ah  = (l >> 4) & 1;                   // A: k-half
#pragma unroll
        for (int mt = 0; mt < 2; mt++) {
            int row = wm + mt * 16 + mrl;
            apre[mt] = sb + row * 64 + ((ah ^ ((row >> 1) & 3)) << 4);
        }
        const int nrl = ((l >> 4) & 1) * 8 + (l & 7);   // B: row-low bits
        const int bh  = (l >> 3) & 1;                   // B: k-half
#pragma unroll
        for (int p = 0; p < 4; p++) {
            int row = wn + p * 16 + nrl;
            bpre[p] = sb + 16384 + row * 64 + ((bh ^ ((row >> 1) & 3)) << 4);
        }
    }

    // ---- loader precompute: 2 A chunks + 2 B chunks per thread ----
    // chunk c = 2*tid+u : row = c>>2, cc = c&3 (16B chunk within row)
    uint32_t a_off[2], b_off[2];
    const float*  aF[2];  const __half* aH[2];  bool aok[2];
    const __half* bS[2];
#pragma unroll
    for (int u = 0; u < 2; u++) {
        int c = tid * 2 + u;
        int row = c >> 2, cc = c & 3;
        a_off[u] = (uint32_t)(row * 64 + ((cc ^ ((row >> 1) & 3)) << 4));
        b_off[u] = (uint32_t)(16384 + row * 64 + ((cc ^ ((row >> 1) & 3)) << 4));
        aok[u] = (bm + row) < M;
        if (AHALF) aH[u] = (const __half*)Araw + (size_t)(bm + row) * 256 + cc * 8;
        else       aF[u] = (const float*) Araw + (size_t)(bm + row) * 256 + cc * 8;
        bS[u] = Bt + (size_t)(bn + row) * 256 + cc * 8;
    }

    float acc[2][8][4];
#pragma unroll
    for (int mt = 0; mt < 2; mt++)
#pragma unroll
        for (int nt = 0; nt < 8; nt++)
#pragma unroll
            for (int q = 0; q < 4; q++) acc[mt][nt][q] = 0.0f;

    uint4  pah[2];  float4 paf[2][2];  uint4 pbv[2];

    auto fetch = [&](int t) {
        const int ko = t * 32;
#pragma unroll
        for (int u = 0; u < 2; u++) {
            if (AHALF) {
                pah[u] = aok[u] ? *reinterpret_cast<const uint4*>(aH[u] + ko)
                                : make_uint4(0u, 0u, 0u, 0u);
            } else {
                if (aok[u]) {
                    paf[u][0] = *reinterpret_cast<const float4*>(aF[u] + ko);
                    paf[u][1] = *reinterpret_cast<const float4*>(aF[u] + ko + 4);
                } else {
                    paf[u][0] = paf[u][1] = make_float4(0.f, 0.f, 0.f, 0.f);
                }
            }
            pbv[u] = *reinterpret_cast<const uint4*>(bS[u] + ko);
        }
    };
    auto store = [&](int buf) {
        const uint32_t bo = (uint32_t)buf * 8192;
#pragma unroll
        for (int u = 0; u < 2; u++) {
            uint4 w;
            if (AHALF) {
                w = pah[u];
            } else {
                w.x = f2h2(paf[u][0].x, paf[u][0].y);
                w.y = f2h2(paf[u][0].z, paf[u][0].w);
                w.z = f2h2(paf[u][1].x, paf[u][1].y);
                w.w = f2h2(paf[u][1].z, paf[u][1].w);
            }
            *reinterpret_cast<uint4*>(sm + bo + a_off[u]) = w;
            *reinterpret_cast<uint4*>(sm + bo + b_off[u]) = pbv[u];
        }
    };

    fetch(0);
    store(0);
    __syncthreads();

    const int nk = 256 / 32;
    int cur = 0;
    for (int t = 0; t < nk; t++) {
        if (t + 1 < nk) fetch(t + 1);

        const uint32_t bo = (uint32_t)cur * 8192;
#pragma unroll
        for (int ks = 0; ks < 2; ks++) {
            const uint32_t kx = (uint32_t)ks << 5;
            uint32_t af[2][4];
#pragma unroll
            for (int mt = 0; mt < 2; mt++)
                ldsm4((apre[mt] + bo) ^ kx, af[mt]);
            uint32_t bf[8][2];
#pragma unroll
            for (int p = 0; p < 4; p++) {
                uint32_t b4[4];
                ldsm4((bpre[p] + bo) ^ kx, b4);
                bf[2 * p][0] = b4[0]; bf[2 * p][1] = b4[1];
                bf[2 * p + 1][0] = b4[2]; bf[2 * p + 1][1] = b4[3];
            }
#pragma unroll
            for (int mt = 0; mt < 2; mt++)
#pragma unroll
                for (int nt = 0; nt < 8; nt++)
                    mma_f16(acc[mt][nt],
                            af[mt][0], af[mt][1], af[mt][2], af[mt][3],
                            bf[nt][0], bf[nt][1]);
        }

        if (t + 1 < nk) {
            store(cur ^ 1);
            __syncthreads();
            cur ^= 1;
        }
    }

    // ---- epilogue ----
    const int g = lane >> 2, tig = lane & 3;
#pragma unroll
    for (int mt = 0; mt < 2; mt++) {
        int r0 = bm + wm + mt * 16 + g;
        int r1 = r0 + 8;
        float s0 = 1.0f, s1 = 1.0f;
        if (SCALE) {
            s0 = (r0 < M) ? g_dinv[r0] : 0.0f;
            s1 = (r1 < M) ? g_dinv[r1] : 0.0f;
        }
#pragma unroll
        for (int nt = 0; nt < 8; nt++) {
            int c = bn + wn + nt * 8 + 2 * tig;
            if (r0 < M)
                *reinterpret_cast<__half2*>(Yh + (size_t)r0 * Nrow + c) =
                    __floats2half2_rn(s0 * acc[mt][nt][0], s0 * acc[mt][nt][1]);
            if (r1 < M)
                *reinterpret_cast<__half2*>(Yh + (size_t)r1 * Nrow + c) =
                    __floats2half2_rn(s1 * acc[mt][nt][2], s1 * acc[mt][nt][3]);
        }
    }
}

// gemm1: unscaled y1, degree-count fused into block tail
__global__ __launch_bounds__(256) void gemm1_kernel(const float* __restrict__ z,
                                                    const int* __restrict__ ei,
                                                    int n_edges, int M)
{
    gemm_body<false, false>(z, g_w1t, g_y1h, M, D_HID);

    const int nb  = gridDim.x * gridDim.y;
    const int bid = blockIdx.y * gridDim.x + blockIdx.x;
    const int per = (n_edges + nb - 1) / nb;
    const int e1  = min((bid + 1) * per, n_edges);
    for (int e = bid * per + threadIdx.x; e < e1; e += 256)
        atomicAdd(&g_cnt[ei[n_edges + e]], 1);
}

__global__ __launch_bounds__(256) void gemm2_kernel(int M)
{
    gemm_body<true, true>(g_hh, g_w2t, g_y2h, M, D_OUT);
}

// ---------------------------------------------------------------------------
// CSR aggregation. agg1 applies dinv[s] per edge (y1 unscaled).
// ---------------------------------------------------------------------------
__device__ __forceinline__ void h8_fma(float a[8], uint4 u, float d) {
    float2 f;
    f = __half22float2(*reinterpret_cast<const __half2*>(&u.x));
    a[0] = fmaf(d, f.x, a[0]); a[1] = fmaf(d, f.y, a[1]);
    f = __half22float2(*reinterpret_cast<const __half2*>(&u.y));
    a[2] = fmaf(d, f.x, a[2]); a[3] = fmaf(d, f.y, a[3]);
    f = __half22float2(*reinterpret_cast<const __half2*>(&u.z));
    a[4] = fmaf(d, f.x, a[4]); a[5] = fmaf(d, f.y, a[5]);
    f = __half22float2(*reinterpret_cast<const __half2*>(&u.w));
    a[6] = fmaf(d, f.x, a[6]); a[7] = fmaf(d, f.y, a[7]);
}
__device__ __forceinline__ void h4_add(float a[4], uint2 u) {
    float2 f;
    f = __half22float2(*reinterpret_cast<const __half2*>(&u.x));
    a[0] += f.x; a[1] += f.y;
    f = __half22float2(*reinterpret_cast<const __half2*>(&u.y));
    a[2] += f.x; a[3] += f.y;
}

__global__ __launch_bounds__(256) void agg1_kernel(const float* __restrict__ bias,
                                                   int n_nodes)
{
    const int node = (blockIdx.x * blockDim.x + threadIdx.x) >> 5;
    const int lane = threadIdx.x & 31;
    if (node >= n_nodes) return;

    const uint4* Yv = reinterpret_cast<const uint4*>(g_y1h);
    const float sself = g_dinv[node];

    float a[8];
    {
        uint4 u = Yv[(size_t)node * 32 + lane];
        float2 f;
        f = __half22float2(*reinterpret_cast<const __half2*>(&u.x));
        a[0] = sself * f.x; a[1] = sself * f.y;
        f = __half22float2(*reinterpret_cast<const __half2*>(&u.y));
        a[2] = sself * f.x; a[3] = sself * f.y;
        f = __half22float2(*reinterpret_cast<const __half2*>(&u.z));
        a[4] = sself * f.x; a[5] = sself * f.y;
        f = __half22float2(*reinterpret_cast<const __half2*>(&u.w));
        a[6] = sself * f.x; a[7] = sself * f.y;
    }
    const int e0 = g_rowptr[node];
    const int e1 = g_rowptr[node + 1];

    int e = e0;
    if (e + 1 < e1) {
        int s0 = g_col[e], s1 = g_col[e + 1];
        uint4 v0 = Yv[(size_t)s0 * 32 + lane];
        uint4 v1 = Yv[(size_t)s1 * 32 + lane];
        float d0 = g_dinv[s0], d1 = g_dinv[s1];
        e += 2;
        for (; e + 1 < e1; e += 2) {
            int n0 = g_col[e], n1 = g_col[e + 1];
            uint4 w0 = Yv[(size_t)n0 * 32 + lane];
            uint4 w1 = Yv[(size_t)n1 * 32 + lane];
            float dd0 = g_dinv[n0], dd1 = g_dinv[n1];
            h8_fma(a, v0, d0); h8_fma(a, v1, d1);
            v0 = w0; v1 = w1; d0 = dd0; d1 = dd1;
        }
        h8_fma(a, v0, d0); h8_fma(a, v1, d1);
    }
    if (e < e1) {
        int s = g_col[e];
        h8_fma(a, Yv[(size_t)s * 32 + lane], g_dinv[s]);
    }

    const float4* bv = reinterpret_cast<const float4*>(bias);
    float4 b0 = bv[lane * 2], b1 = bv[lane * 2 + 1];
    float o[8];
    o[0] = fmaxf(fmaf(sself, a[0], b0.x), 0.f);
    o[1] = fmaxf(fmaf(sself, a[1], b0.y), 0.f);
    o[2] = fmaxf(fmaf(sself, a[2], b0.z), 0.f);
    o[3] = fmaxf(fmaf(sself, a[3], b0.w), 0.f);
    o[4] = fmaxf(fmaf(sself, a[4], b1.x), 0.f);
    o[5] = fmaxf(fmaf(sself, a[5], b1.y), 0.f);
    o[6] = fmaxf(fmaf(sself, a[6], b1.z), 0.f);
    o[7] = fmaxf(fmaf(sself, a[7], b1.w), 0.f);
    uint4 w;
    w.x = f2h2(o[0], o[1]); w.y = f2h2(o[2], o[3]);
    w.z = f2h2(o[4], o[5]); w.w = f2h2(o[6], o[7]);
    reinterpret_cast<uint4*>(g_hh + (size_t)node * 256)[lane] = w;
}

__global__ __launch_bounds__(256) void agg2_kernel(float* __restrict__ out,
                                                   const float* __restrict__ bias,
                                                   int n_nodes)
{
    const int node = (blockIdx.x * blockDim.x + threadIdx.x) >> 5;
    const int lane = threadIdx.x & 31;
    if (node >= n_nodes) return;

    const uint2* Yv = reinterpret_cast<const uint2*>(g_y2h);
    float a[4];
    {
        uint2 u = Yv[(size_t)node * 32 + lane];
        float2 f;
        f = __half22float2(*reinterpret_cast<const __half2*>(&u.x));
        a[0] = f.x; a[1] = f.y;
        f = __half22float2(*reinterpret_cast<const __half2*>(&u.y));
        a[2] = f.x; a[3] = f.y;
    }
    const int e0 = g_rowptr[node];
    const int e1 = g_rowptr[node + 1];

    int e = e0;
    if (e + 1 < e1) {
        uint2 v0 = Yv[(size_t)g_col[e]     * 32 + lane];
        uint2 v1 = Yv[(size_t)g_col[e + 1] * 32 + lane];
        e += 2;
        for (; e + 1 < e1; e += 2) {
            uint2 w0 = Yv[(size_t)g_col[e]     * 32 + lane];
            uint2 w1 = Yv[(size_t)g_col[e + 1] * 32 + lane];
            h4_add(a, v0); h4_add(a, v1);
            v0 = w0; v1 = w1;
        }
        h4_add(a, v0); h4_add(a, v1);
    }
    if (e < e1) h4_add(a, Yv[(size_t)g_col[e] * 32 + lane]);

    const float s = g_dinv[node];
    float4 b = reinterpret_cast<const float4*>(bias)[lane];
    float4 o;
    o.x = fmaf(s, a[0], b.x);
    o.y = fmaf(s, a[1], b.y);
    o.z = fmaf(s, a[2], b.z);
    o.w = fmaf(s, a[3], b.w);
    reinterpret_cast<float4*>(out + (size_t)node * 128)[lane] = o;
}

// ---------------------------------------------------------------------------
extern "C" void kernel_launch(void* const* d_in, const int* in_sizes, int n_in,
                              void* d_out, int out_size)
{
    const float* z   = (const float*)d_in[0];
    const int*   ei  = (const int*)  d_in[1];
    const float* W1  = (const float*)d_in[2];
    const float* b1  = (const float*)d_in[3];
    const float* W2  = (const float*)d_in[4];
    const float* b2  = (const float*)d_in[5];
    float* out = (float*)d_out;

    const int n_nodes = in_sizes[0] / D_IN;
    const int n_edges = in_sizes[1] / 2;
    const int T   = 256;
    const int nbN = (n_nodes + T - 1) / T;
    const int nbE = (n_edges + T - 1) / T;

    const int prepN = n_nodes + D_HID * D_IN + D_OUT * D_HID;
    prep_kernel<<<(prepN + T - 1) / T, T>>>(W1, W2, n_nodes);

    const unsigned gx = (unsigned)((n_nodes + 127) / 128);

    // gemm1 (+ fused degree count)
    gemm1_kernel<<<dim3(gx, D_HID / 128), T>>>(z, ei, n_edges, n_nodes);

    // CSR build tail
    scan1_kernel<<<nbN, T>>>(n_nodes);
    scan2_kernel<<<1, T>>>(nbN);
    scan3_kernel<<<nbN, T>>>(n_nodes);
    fill_kernel<<<nbE, T>>>(ei, n_edges);

    const unsigned aggB = (unsigned)(((long long)n_nodes * 32 + T - 1) / T);
    agg1_kernel<<<aggB, T>>>(b1, n_nodes);

    gemm2_kernel<<<dim3(gx, D_OUT / 128), T>>>(n_nodes);
    agg2_kernel<<<aggB, T>>>(out, b2, n_nodes);
}

// round 12
// speedup vs baseline: 2.5944x; 1.0452x over previous
#include <cuda_runtime.h>
#include <cuda_fp16.h>
#include <cstdint>

// ---------------------------------------------------------------------------
// 2-layer GCN (sm_103: mma.sync HMMA; tcgen05 not available in this build).
//   y1 = z W1 (UNSCALED fp16)  -- ldmatrix m16n8k16 GEMM
//   h  = relu(dinv[d]*(dinv[d]*y1[d] + sum dinv[s]*y1[s]) + b1)
//   y2 = dinv * (h W2) (fp16)
//   out= dinv[d]*(y2[d] + sum y2[s]) + b2
// CSR build (count/scan/fill) runs CONCURRENTLY with gemm1 on a forked
// stream (graph fork/join via events); joins before agg1.
// RULE: __device__ globals only referenced from device code.
// ---------------------------------------------------------------------------

#define MAX_NODES 50048
#define MAX_EDGES 1048576
#define D_IN   256
#define D_HID  256
#define D_OUT  128
#define SCAN_B ((MAX_NODES + 255) / 256)

__device__ float  g_dinv[MAX_NODES];
__device__ int    g_cnt [MAX_NODES];
__device__ int    g_tmp [MAX_NODES];
__device__ int    g_bsum[SCAN_B];
__device__ int    g_rowptr[MAX_NODES + 1];
__device__ int    g_wofs[MAX_NODES];
__device__ int    g_col [MAX_EDGES];
__device__ __half g_y1h[(size_t)MAX_NODES * D_HID];   // UNSCALED z@W1
__device__ __half g_hh [(size_t)MAX_NODES * D_HID];
__device__ __half g_y2h[(size_t)MAX_NODES * D_OUT];   // dinv-scaled h@W2
__device__ __half g_w1t[D_HID * D_IN];
__device__ __half g_w2t[D_OUT * D_HID];

// ---------------------------------------------------------------------------
__device__ __forceinline__ uint32_t smem_u32(const void* p) {
    uint32_t a;
    asm("{ .reg .u64 t; cvta.to.shared.u64 t, %1; cvt.u32.u64 %0, t; }"
        : "=r"(a) : "l"(p));
    return a;
}

__device__ __forceinline__ unsigned f2h2(float lo, float hi) {
    __half2 h = __floats2half2_rn(lo, hi);
    return *reinterpret_cast<unsigned*>(&h);
}

__device__ __forceinline__ void mma_f16(float c[4],
                                        unsigned a0, unsigned a1,
                                        unsigned a2, unsigned a3,
                                        unsigned b0, unsigned b1) {
    asm volatile(
        "mma.sync.aligned.m16n8k16.row.col.f32.f16.f16.f32 "
        "{%0,%1,%2,%3}, {%4,%5,%6,%7}, {%8,%9}, {%0,%1,%2,%3};"
        : "+f"(c[0]), "+f"(c[1]), "+f"(c[2]), "+f"(c[3])
        : "r"(a0), "r"(a1), "r"(a2), "r"(a3), "r"(b0), "r"(b1));
}

__device__ __forceinline__ void ldsm4(uint32_t addr, uint32_t r[4]) {
    asm volatile("ldmatrix.sync.aligned.m8n8.x4.shared.b16 {%0,%1,%2,%3}, [%4];"
                 : "=r"(r[0]), "=r"(r[1]), "=r"(r[2]), "=r"(r[3]) : "r"(addr));
}

// ---------------------------------------------------------------------------
// prep: zero degree counters + pack W1^T, W2^T fp16
// ---------------------------------------------------------------------------
__global__ void prep_kernel(const float* __restrict__ W1,
                            const float* __restrict__ W2, int n_nodes) {
    int i = blockIdx.x * blockDim.x + threadIdx.x;
    if (i < n_nodes) { g_cnt[i] = 0; return; }
    int j = i - n_nodes;
    if (j < D_HID * D_IN) {
        int n = j >> 8, k = j & 255;
        g_w1t[j] = __float2half_rn(W1[k * D_HID + n]);
        return;
    }
    j -= D_HID * D_IN;
    if (j < D_OUT * D_HID) {
        int n = j >> 8, k = j & 255;
        g_w2t[j] = __float2half_rn(W2[k * D_OUT + n]);
    }
}

// ---------------------------------------------------------------------------
// CSR build chain (runs on forked stream)
// ---------------------------------------------------------------------------
__global__ void count_kernel(const int* __restrict__ ei, int n_edges) {
    int e = blockIdx.x * blockDim.x + threadIdx.x;
    if (e < n_edges) atomicAdd(&g_cnt[ei[n_edges + e]], 1);
}
__global__ void scan1_kernel(int n) {
    __shared__ int sh[256];
    int i = blockIdx.x * 256 + threadIdx.x;
    int v = (i < n) ? g_cnt[i] : 0;
    sh[threadIdx.x] = v;
    __syncthreads();
#pragma unroll
    for (int off = 1; off < 256; off <<= 1) {
        int t = (threadIdx.x >= off) ? sh[threadIdx.x - off] : 0;
        __syncthreads();
        sh[threadIdx.x] += t;
        __syncthreads();
    }
    if (i < n) g_tmp[i] = sh[threadIdx.x];
    if (threadIdx.x == 255) g_bsum[blockIdx.x] = sh[255];
}
__global__ void scan2_kernel(int nb) {
    __shared__ int sh[256];
    int t = threadIdx.x;
    int v = (t < nb) ? g_bsum[t] : 0;
    sh[t] = v;
    __syncthreads();
#pragma unroll
    for (int off = 1; off < 256; off <<= 1) {
        int u = (t >= off) ? sh[t - off] : 0;
        __syncthreads();
        sh[t] += u;
        __syncthreads();
    }
    int ex = (t == 0) ? 0 : sh[t - 1];
    if (t < nb) g_bsum[t] = ex;
}
__global__ void scan3_kernel(int n) {
    int i = blockIdx.x * 256 + threadIdx.x;
    if (i < n) {
        int incl = g_tmp[i] + g_bsum[blockIdx.x];
        g_rowptr[i + 1] = incl;
        g_wofs[i] = incl - g_cnt[i];
        g_dinv[i] = rsqrtf((float)(g_cnt[i] + 1));
        if (i == 0) g_rowptr[0] = 0;
    }
}
__global__ void fill_kernel(const int* __restrict__ ei, int n_edges) {
    int e = blockIdx.x * blockDim.x + threadIdx.x;
    if (e < n_edges) {
        int dst = ei[n_edges + e];
        int pos = atomicAdd(&g_wofs[dst], 1);
        g_col[pos] = ei[e];
    }
}

// ---------------------------------------------------------------------------
// fp16 mma GEMM with ldmatrix fragment loads (round-11 proven).
// BM=128, BN=128, BK=32, 256 threads, warp grid 4m x 2n, warp 32x64.
// Smem: row-major 64B pitch, 16B-chunk swizzle chunk^=((row>>1)&3).
// ---------------------------------------------------------------------------
template<bool AHALF, bool SCALE>
__device__ __forceinline__ void gemm_body(const void* __restrict__ Araw,
                                          const __half* __restrict__ Bt,
                                          __half* __restrict__ Yh,
                                          int M, int Nrow)
{
    __shared__ __align__(128) char sm[32768];
    const uint32_t sb = smem_u32(sm);
    const int tid  = threadIdx.x;
    const int lane = tid & 31;
    const int warp = tid >> 5;
    const int bm   = blockIdx.x * 128;
    const int bn   = blockIdx.y * 128;
    const int wm   = (warp & 3) * 32;
    const int wn   = (warp >> 2) * 64;

    uint32_t apre[2], bpre[4];
    {
        const int l = lane;
        const int mrl = ((l >> 3) & 1) * 8 + (l & 7);
        const int ah  = (l >> 4) & 1;
#pragma unroll
        for (int mt = 0; mt < 2; mt++) {
            int row = wm + mt * 16 + mrl;
            apre[mt] = sb + row * 64 + ((ah ^ ((row >> 1) & 3)) << 4);
        }
        const int nrl = ((l >> 4) & 1) * 8 + (l & 7);
        const int bh  = (l >> 3) & 1;
#pragma unroll
        for (int p = 0; p < 4; p++) {
            int row = wn + p * 16 + nrl;
            bpre[p] = sb + 16384 + row * 64 + ((bh ^ ((row >> 1) & 3)) << 4);
        }
    }

    uint32_t a_off[2], b_off[2];
    const float*  aF[2];  const __half* aH[2];  bool aok[2];
    const __half* bS[2];
#pragma unroll
    for (int u = 0; u < 2; u++) {
        int c = tid * 2 + u;
        int row = c >> 2, cc = c & 3;
        a_off[u] = (uint32_t)(row * 64 + ((cc ^ ((row >> 1) & 3)) << 4));
        b_off[u] = (uint32_t)(16384 + row * 64 + ((cc ^ ((row >> 1) & 3)) << 4));
        aok[u] = (bm + row) < M;
        if (AHALF) aH[u] = (const __half*)Araw + (size_t)(bm + row) * 256 + cc * 8;
        else       aF[u] = (const float*) Araw + (size_t)(bm + row) * 256 + cc * 8;
        bS[u] = Bt + (size_t)(bn + row) * 256 + cc * 8;
    }

    float acc[2][8][4];
#pragma unroll
    for (int mt = 0; mt < 2; mt++)
#pragma unroll
        for (int nt = 0; nt < 8; nt++)
#pragma unroll
            for (int q = 0; q < 4; q++) acc[mt][nt][q] = 0.0f;

    uint4  pah[2];  float4 paf[2][2];  uint4 pbv[2];

    auto fetch = [&](int t) {
        const int ko = t * 32;
#pragma unroll
        for (int u = 0; u < 2; u++) {
            if (AHALF) {
                pah[u] = aok[u] ? *reinterpret_cast<const uint4*>(aH[u] + ko)
                                : make_uint4(0u, 0u, 0u, 0u);
            } else {
                if (aok[u]) {
                    paf[u][0] = *reinterpret_cast<const float4*>(aF[u] + ko);
                    paf[u][1] = *reinterpret_cast<const float4*>(aF[u] + ko + 4);
                } else {
                    paf[u][0] = paf[u][1] = make_float4(0.f, 0.f, 0.f, 0.f);
                }
            }
            pbv[u] = *reinterpret_cast<const uint4*>(bS[u] + ko);
        }
    };
    auto store = [&](int buf) {
        const uint32_t bo = (uint32_t)buf * 8192;
#pragma unroll
        for (int u = 0; u < 2; u++) {
            uint4 w;
            if (AHALF) {
                w = pah[u];
            } else {
                w.x = f2h2(paf[u][0].x, paf[u][0].y);
                w.y = f2h2(paf[u][0].z, paf[u][0].w);
                w.z = f2h2(paf[u][1].x, paf[u][1].y);
                w.w = f2h2(paf[u][1].z, paf[u][1].w);
            }
            *reinterpret_cast<uint4*>(sm + bo + a_off[u]) = w;
            *reinterpret_cast<uint4*>(sm + bo + b_off[u]) = pbv[u];
        }
    };

    fetch(0);
    store(0);
    __syncthreads();

    const int nk = 256 / 32;
    int cur = 0;
    for (int t = 0; t < nk; t++) {
        if (t + 1 < nk) fetch(t + 1);

        const uint32_t bo = (uint32_t)cur * 8192;
#pragma unroll
        for (int ks = 0; ks < 2; ks++) {
            const uint32_t kx = (uint32_t)ks << 5;
            uint32_t af[2][4];
#pragma unroll
            for (int mt = 0; mt < 2; mt++)
                ldsm4((apre[mt] + bo) ^ kx, af[mt]);
            uint32_t bf[8][2];
#pragma unroll
            for (int p = 0; p < 4; p++) {
                uint32_t b4[4];
                ldsm4((bpre[p] + bo) ^ kx, b4);
                bf[2 * p][0] = b4[0]; bf[2 * p][1] = b4[1];
                bf[2 * p + 1][0] = b4[2]; bf[2 * p + 1][1] = b4[3];
            }
#pragma unroll
            for (int mt = 0; mt < 2; mt++)
#pragma unroll
                for (int nt = 0; nt < 8; nt++)
                    mma_f16(acc[mt][nt],
                            af[mt][0], af[mt][1], af[mt][2], af[mt][3],
                            bf[nt][0], bf[nt][1]);
        }

        if (t + 1 < nk) {
            store(cur ^ 1);
            __syncthreads();
            cur ^= 1;
        }
    }

    const int g = lane >> 2, tig = lane & 3;
#pragma unroll
    for (int mt = 0; mt < 2; mt++) {
        int r0 = bm + wm + mt * 16 + g;
        int r1 = r0 + 8;
        float s0 = 1.0f, s1 = 1.0f;
        if (SCALE) {
            s0 = (r0 < M) ? g_dinv[r0] : 0.0f;
            s1 = (r1 < M) ? g_dinv[r1] : 0.0f;
        }
#pragma unroll
        for (int nt = 0; nt < 8; nt++) {
            int c = bn + wn + nt * 8 + 2 * tig;
            if (r0 < M)
                *reinterpret_cast<__half2*>(Yh + (size_t)r0 * Nrow + c) =
                    __floats2half2_rn(s0 * acc[mt][nt][0], s0 * acc[mt][nt][1]);
            if (r1 < M)
                *reinterpret_cast<__half2*>(Yh + (size_t)r1 * Nrow + c) =
                    __floats2half2_rn(s1 * acc[mt][nt][2], s1 * acc[mt][nt][3]);
        }
    }
}

__global__ __launch_bounds__(256) void gemm1_kernel(const float* __restrict__ z,
                                                    int M)
{
    gemm_body<false, false>(z, g_w1t, g_y1h, M, D_HID);
}

__global__ __launch_bounds__(256) void gemm2_kernel(int M)
{
    gemm_body<true, true>(g_hh, g_w2t, g_y2h, M, D_OUT);
}

// ---------------------------------------------------------------------------
// CSR aggregation (round-11 proven; agg1 applies dinv[s] per edge)
// ---------------------------------------------------------------------------
__device__ __forceinline__ void h8_fma(float a[8], uint4 u, float d) {
    float2 f;
    f = __half22float2(*reinterpret_cast<const __half2*>(&u.x));
    a[0] = fmaf(d, f.x, a[0]); a[1] = fmaf(d, f.y, a[1]);
    f = __half22float2(*reinterpret_cast<const __half2*>(&u.y));
    a[2] = fmaf(d, f.x, a[2]); a[3] = fmaf(d, f.y, a[3]);
    f = __half22float2(*reinterpret_cast<const __half2*>(&u.z));
    a[4] = fmaf(d, f.x, a[4]); a[5] = fmaf(d, f.y, a[5]);
    f = __half22float2(*reinterpret_cast<const __half2*>(&u.w));
    a[6] = fmaf(d, f.x, a[6]); a[7] = fmaf(d, f.y, a[7]);
}
__device__ __forceinline__ void h4_add(float a[4], uint2 u) {
    float2 f;
    f = __half22float2(*reinterpret_cast<const __half2*>(&u.x));
    a[0] += f.x; a[1] += f.y;
    f = __half22float2(*reinterpret_cast<const __half2*>(&u.y));
    a[2] += f.x; a[3] += f.y;
}

__global__ __launch_bounds__(256) void agg1_kernel(const float* __restrict__ bias,
                                                   int n_nodes)
{
    const int node = (blockIdx.x * blockDim.x + threadIdx.x) >> 5;
    const int lane = threadIdx.x & 31;
    if (node >= n_nodes) return;

    const uint4* Yv = reinterpret_cast<const uint4*>(g_y1h);
    const float sself = g_dinv[node];

    float a[8];
    {
        uint4 u = Yv[(size_t)node * 32 + lane];
        float2 f;
        f = __half22float2(*reinterpret_cast<const __half2*>(&u.x));
        a[0] = sself * f.x; a[1] = sself * f.y;
        f = __half22float2(*reinterpret_cast<const __half2*>(&u.y));
        a[2] = sself * f.x; a[3] = sself * f.y;
        f = __half22float2(*reinterpret_cast<const __half2*>(&u.z));
        a[4] = sself * f.x; a[5] = sself * f.y;
        f = __half22float2(*reinterpret_cast<const __half2*>(&u.w));
        a[6] = sself * f.x; a[7] = sself * f.y;
    }
    const int e0 = g_rowptr[node];
    const int e1 = g_rowptr[node + 1];

    int e = e0;
    if (e + 1 < e1) {
        int s0 = g_col[e], s1 = g_col[e + 1];
        uint4 v0 = Yv[(size_t)s0 * 32 + lane];
        uint4 v1 = Yv[(size_t)s1 * 32 + lane];
        float d0 = g_dinv[s0], d1 = g_dinv[s1];
        e += 2;
        for (; e + 1 < e1; e += 2) {
            int n0 = g_col[e], n1 = g_col[e + 1];
            uint4 w0 = Yv[(size_t)n0 * 32 + lane];
            uint4 w1 = Yv[(size_t)n1 * 32 + lane];
            float dd0 = g_dinv[n0], dd1 = g_dinv[n1];
            h8_fma(a, v0, d0); h8_fma(a, v1, d1);
            v0 = w0; v1 = w1; d0 = dd0; d1 = dd1;
        }
        h8_fma(a, v0, d0); h8_fma(a, v1, d1);
    }
    if (e < e1) {
        int s = g_col[e];
        h8_fma(a, Yv[(size_t)s * 32 + lane], g_dinv[s]);
    }

    const float4* bv = reinterpret_cast<const float4*>(bias);
    float4 b0 = bv[lane * 2], b1 = bv[lane * 2 + 1];
    float o[8];
    o[0] = fmaxf(fmaf(sself, a[0], b0.x), 0.f);
    o[1] = fmaxf(fmaf(sself, a[1], b0.y), 0.f);
    o[2] = fmaxf(fmaf(sself, a[2], b0.z), 0.f);
    o[3] = fmaxf(fmaf(sself, a[3], b0.w), 0.f);
    o[4] = fmaxf(fmaf(sself, a[4], b1.x), 0.f);
    o[5] = fmaxf(fmaf(sself, a[5], b1.y), 0.f);
    o[6] = fmaxf(fmaf(sself, a[6], b1.z), 0.f);
    o[7] = fmaxf(fmaf(sself, a[7], b1.w), 0.f);
    uint4 w;
    w.x = f2h2(o[0], o[1]); w.y = f2h2(o[2], o[3]);
    w.z = f2h2(o[4], o[5]); w.w = f2h2(o[6], o[7]);
    reinterpret_cast<uint4*>(g_hh + (size_t)node * 256)[lane] = w;
}

__global__ __launch_bounds__(256) void agg2_kernel(float* __restrict__ out,
                                                   const float* __restrict__ bias,
                                                   int n_nodes)
{
    const int node = (blockIdx.x * blockDim.x + threadIdx.x) >> 5;
    const int lane = threadIdx.x & 31;
    if (node >= n_nodes) return;

    const uint2* Yv = reinterpret_cast<const uint2*>(g_y2h);
    float a[4];
    {
        uint2 u = Yv[(size_t)node * 32 + lane];
        float2 f;
        f = __half22float2(*reinterpret_cast<const __half2*>(&u.x));
        a[0] = f.x; a[1] = f.y;
        f = __half22float2(*reinterpret_cast<const __half2*>(&u.y));
        a[2] = f.x; a[3] = f.y;
    }
    const int e0 = g_rowptr[node];
    const int e1 = g_rowptr[node + 1];

    int e = e0;
    if (e + 1 < e1) {
        uint2 v0 = Yv[(size_t)g_col[e]     * 32 + lane];
        uint2 v1 = Yv[(size_t)g_col[e + 1] * 32 + lane];
        e += 2;
        for (; e + 1 < e1; e += 2) {
            uint2 w0 = Yv[(size_t)g_col[e]     * 32 + lane];
            uint2 w1 = Yv[(size_t)g_col[e + 1] * 32 + lane];
            h4_add(a, v0); h4_add(a, v1);
            v0 = w0; v1 = w1;
        }
        h4_add(a, v0); h4_add(a, v1);
    }
    if (e < e1) h4_add(a, Yv[(size_t)g_col[e] * 32 + lane]);

    const float s = g_dinv[node];
    float4 b = reinterpret_cast<const float4*>(bias)[lane];
    float4 o;
    o.x = fmaf(s, a[0], b.x);
    o.y = fmaf(s, a[1], b.y);
    o.z = fmaf(s, a[2], b.z);
    o.w = fmaf(s, a[3], b.w);
    reinterpret_cast<float4*>(out + (size_t)node * 128)[lane] = o;
}

// ---------------------------------------------------------------------------
extern "C" void kernel_launch(void* const* d_in, const int* in_sizes, int n_in,
                              void* d_out, int out_size)
{
    const float* z   = (const float*)d_in[0];
    const int*   ei  = (const int*)  d_in[1];
    const float* W1  = (const float*)d_in[2];
    const float* b1  = (const float*)d_in[3];
    const float* W2  = (const float*)d_in[4];
    const float* b2  = (const float*)d_in[5];
    float* out = (float*)d_out;

    const int n_nodes = in_sizes[0] / D_IN;
    const int n_edges = in_sizes[1] / 2;
    const int T   = 256;
    const int nbN = (n_nodes + T - 1) / T;
    const int nbE = (n_edges + T - 1) / T;

    // one-time side-stream + events (host resources, no device allocation;
    // identical captured work on every call)
    static cudaStream_t s2 = nullptr;
    static cudaEvent_t evFork = nullptr, evJoin = nullptr;
    if (s2 == nullptr) {
        cudaStreamCreateWithFlags(&s2, cudaStreamNonBlocking);
        cudaEventCreateWithFlags(&evFork, cudaEventDisableTiming);
        cudaEventCreateWithFlags(&evJoin, cudaEventDisableTiming);
    }

    const int prepN = n_nodes + D_HID * D_IN + D_OUT * D_HID;
    prep_kernel<<<(prepN + T - 1) / T, T>>>(W1, W2, n_nodes);

    // ---- fork: CSR build on s2, gemm1 on main stream ----
    cudaEventRecord(evFork, 0);
    cudaStreamWaitEvent(s2, evFork, 0);

    count_kernel<<<nbE, T, 0, s2>>>(ei, n_edges);
    scan1_kernel<<<nbN, T, 0, s2>>>(n_nodes);
    scan2_kernel<<<1,   T, 0, s2>>>(nbN);
    scan3_kernel<<<nbN, T, 0, s2>>>(n_nodes);
    fill_kernel <<<nbE, T, 0, s2>>>(ei, n_edges);
    cudaEventRecord(evJoin, s2);

    const unsigned gx = (unsigned)((n_nodes + 127) / 128);
    gemm1_kernel<<<dim3(gx, D_HID / 128), T>>>(z, n_nodes);

    // ---- join ----
    cudaStreamWaitEvent(0, evJoin, 0);

    const unsigned aggB = (unsigned)(((long long)n_nodes * 32 + T - 1) / T);
    agg1_kernel<<<aggB, T>>>(b1, n_nodes);
    gemm2_kernel<<<dim3(gx, D_OUT / 128), T>>>(n_nodes);
    agg2_kernel<<<aggB, T>>>(out, b2, n_nodes);
}